// round 1
// baseline (speedup 1.0000x reference)
#include <cuda_runtime.h>
#include <cuda_bf16.h>
#include <cstddef>

// ---------------------------------------------------------------------------
// MLA attention, fp32 baseline.
//   B=2, S=2048, D_MODEL=1024, N_HEADS=16, HEAD_DIM=64, LATENT=256
// Pipeline:
//   1) Q  = x @ Wq  + bq            (4096x1024x1024)
//   2) KL = x @ Wkd + bkd           (4096x1024x256)
//   3) VL = x @ Wvd + bvd           (4096x1024x256)
//   4) K  = KL @ Wku + bku          (4096x256x1024)
//   5) V  = VL @ Wvu + bvu          (4096x256x1024)
//   6) flash attention per (b,h)    -> ctx
//   7) out = ctx @ Wo + bo          (4096x1024x1024)
// ---------------------------------------------------------------------------

#define BATCH    2
#define SEQ      2048
#define DMODEL   1024
#define NHEADS   16
#define HDIM     64
#define LATENT   256
#define MROWS    (BATCH * SEQ)     // 4096

// ------------------------- scratch (device globals) ------------------------
__device__ float g_Q  [MROWS * DMODEL];   // 16 MB
__device__ float g_KL [MROWS * LATENT];   //  4 MB
__device__ float g_VL [MROWS * LATENT];   //  4 MB
__device__ float g_K  [MROWS * DMODEL];   // 16 MB
__device__ float g_V  [MROWS * DMODEL];   // 16 MB
__device__ float g_ctx[MROWS * DMODEL];   // 16 MB

// ------------------------------- SGEMM -------------------------------------
// C[M,N] = A[M,K] @ B[K,N] + bias[N]; all row-major.
// Requires: M % 128 == 0, N % 128 == 0, K % 16 == 0.
#define BM 128
#define BN 128
#define BK 16
#define TM 8
#define TN 8

__global__ __launch_bounds__(256) void sgemm_bias(
    const float* __restrict__ A, const float* __restrict__ B,
    const float* __restrict__ bias, float* __restrict__ C,
    int M, int N, int K)
{
    __shared__ float As[BK][BM];   // A tile, transposed
    __shared__ float Bs[BK][BN];

    const int tid = threadIdx.x;
    const int bx = blockIdx.x, by = blockIdx.y;
    const int tx = tid & 15;       // 16 col-groups of 8
    const int ty = tid >> 4;       // 16 row-groups of 8

    const float* Ab = A + (size_t)by * BM * K;
    const float* Bb = B + (size_t)bx * BN;

    float acc[TM][TN];
    #pragma unroll
    for (int i = 0; i < TM; i++)
        #pragma unroll
        for (int j = 0; j < TN; j++) acc[i][j] = 0.f;

    for (int k0 = 0; k0 < K; k0 += BK) {
        // A tile: 128x16 = 512 float4
        #pragma unroll
        for (int p = 0; p < 2; p++) {
            int f4  = tid + p * 256;        // 0..511
            int row = f4 >> 2;              // 0..127
            int c4  = (f4 & 3) << 2;        // 0,4,8,12
            float4 v = *(const float4*)(Ab + (size_t)row * K + k0 + c4);
            As[c4 + 0][row] = v.x;
            As[c4 + 1][row] = v.y;
            As[c4 + 2][row] = v.z;
            As[c4 + 3][row] = v.w;
        }
        // B tile: 16x128 = 512 float4
        #pragma unroll
        for (int p = 0; p < 2; p++) {
            int f4  = tid + p * 256;
            int row = f4 >> 5;              // 0..15
            int c4  = (f4 & 31) << 2;       // 0..124
            *(float4*)(&Bs[row][c4]) =
                *(const float4*)(Bb + (size_t)(k0 + row) * N + c4);
        }
        __syncthreads();

        #pragma unroll
        for (int kk = 0; kk < BK; kk++) {
            float ra[TM], rb[TN];
            *(float4*)(&ra[0]) = *(const float4*)(&As[kk][ty * TM + 0]);
            *(float4*)(&ra[4]) = *(const float4*)(&As[kk][ty * TM + 4]);
            *(float4*)(&rb[0]) = *(const float4*)(&Bs[kk][tx * TN + 0]);
            *(float4*)(&rb[4]) = *(const float4*)(&Bs[kk][tx * TN + 4]);
            #pragma unroll
            for (int i = 0; i < TM; i++)
                #pragma unroll
                for (int j = 0; j < TN; j++)
                    acc[i][j] = fmaf(ra[i], rb[j], acc[i][j]);
        }
        __syncthreads();
    }

    #pragma unroll
    for (int i = 0; i < TM; i++) {
        int row = by * BM + ty * TM + i;
        #pragma unroll
        for (int j = 0; j < TN; j += 4) {
            int col = bx * BN + tx * TN + j;
            float4 o;
            o.x = acc[i][j + 0] + bias[col + 0];
            o.y = acc[i][j + 1] + bias[col + 1];
            o.z = acc[i][j + 2] + bias[col + 2];
            o.w = acc[i][j + 3] + bias[col + 3];
            *(float4*)(C + (size_t)row * N + col) = o;
        }
    }
}

// --------------------------- flash attention --------------------------------
// grid: (SEQ/64, BATCH*NHEADS), 256 threads.
// Each block: 64 q-rows of one (b,h); loops over 32 k-tiles of 64 keys.
// Layout per thread: tx = tid%16 owns 4 cols, ty = tid/16 owns 4 rows.
__global__ __launch_bounds__(256) void flash_attn(
    const float* __restrict__ Q, const float* __restrict__ K,
    const float* __restrict__ V, float* __restrict__ ctx)
{
    __shared__ float Qs [64][64];
    __shared__ float KPs[64][64];   // K^T during QK, then P
    __shared__ float Vs [64][64];

    const int tid = threadIdx.x;
    const int tx = tid & 15;
    const int ty = tid >> 4;
    const int qt = blockIdx.x;              // 0..31
    const int bh = blockIdx.y;              // 0..31
    const int b  = bh >> 4;
    const int h  = bh & 15;

    const float scale = 0.125f;             // 1/sqrt(64)
    const size_t base = (size_t)b * SEQ * DMODEL + (size_t)h * HDIM;
    const float* Qg = Q + base + (size_t)qt * 64 * DMODEL;
    const float* Kg = K + base;
    const float* Vg = V + base;

    // load Q tile (64 x 64)
    #pragma unroll
    for (int p = 0; p < 4; p++) {
        int f4 = tid + p * 256;              // 0..1023
        int r  = f4 >> 4;
        int c4 = (f4 & 15) << 2;
        *(float4*)(&Qs[r][c4]) = *(const float4*)(Qg + (size_t)r * DMODEL + c4);
    }

    float m[4], l[4], o[4][4];
    #pragma unroll
    for (int i = 0; i < 4; i++) {
        m[i] = -1e30f; l[i] = 0.f;
        #pragma unroll
        for (int j = 0; j < 4; j++) o[i][j] = 0.f;
    }
    __syncthreads();

    for (int kt = 0; kt < 32; kt++) {
        // load K (transposed into KPs) and V (direct)
        #pragma unroll
        for (int p = 0; p < 4; p++) {
            int f4 = tid + p * 256;
            int r  = f4 >> 4;
            int c4 = (f4 & 15) << 2;
            const size_t gro = (size_t)(kt * 64 + r) * DMODEL + c4;
            float4 kv = *(const float4*)(Kg + gro);
            KPs[c4 + 0][r] = kv.x;
            KPs[c4 + 1][r] = kv.y;
            KPs[c4 + 2][r] = kv.z;
            KPs[c4 + 3][r] = kv.w;
            *(float4*)(&Vs[r][c4]) = *(const float4*)(Vg + gro);
        }
        __syncthreads();

        // S = (Q @ K^T) * scale, 4x4 per thread
        float s[4][4];
        #pragma unroll
        for (int i = 0; i < 4; i++)
            #pragma unroll
            for (int j = 0; j < 4; j++) s[i][j] = 0.f;

        #pragma unroll
        for (int d = 0; d < 64; d++) {
            float rq[4];
            #pragma unroll
            for (int i = 0; i < 4; i++) rq[i] = Qs[ty * 4 + i][d];
            float4 rk = *(const float4*)(&KPs[d][tx * 4]);
            #pragma unroll
            for (int i = 0; i < 4; i++) {
                s[i][0] = fmaf(rq[i], rk.x, s[i][0]);
                s[i][1] = fmaf(rq[i], rk.y, s[i][1]);
                s[i][2] = fmaf(rq[i], rk.z, s[i][2]);
                s[i][3] = fmaf(rq[i], rk.w, s[i][3]);
            }
        }

        // online softmax (row reductions over the 16 tx lanes = half-warp)
        #pragma unroll
        for (int i = 0; i < 4; i++) {
            float mx = fmaxf(fmaxf(s[i][0], s[i][1]), fmaxf(s[i][2], s[i][3])) * scale;
            #pragma unroll
            for (int off = 8; off >= 1; off >>= 1)
                mx = fmaxf(mx, __shfl_xor_sync(0xffffffffu, mx, off));
            float mn = fmaxf(m[i], mx);
            float f  = __expf(m[i] - mn);
            l[i] *= f;
            #pragma unroll
            for (int j = 0; j < 4; j++) o[i][j] *= f;
            float rs = 0.f;
            #pragma unroll
            for (int j = 0; j < 4; j++) {
                s[i][j] = __expf(fmaf(s[i][j], scale, -mn));
                rs += s[i][j];
            }
            #pragma unroll
            for (int off = 8; off >= 1; off >>= 1)
                rs += __shfl_xor_sync(0xffffffffu, rs, off);
            l[i] += rs;
            m[i] = mn;
        }

        __syncthreads();   // everyone done reading KPs as K^T
        #pragma unroll
        for (int i = 0; i < 4; i++)
            *(float4*)(&KPs[ty * 4 + i][tx * 4]) =
                make_float4(s[i][0], s[i][1], s[i][2], s[i][3]);
        __syncthreads();   // P visible

        // O += P @ V
        #pragma unroll
        for (int k = 0; k < 64; k++) {
            float rp[4];
            #pragma unroll
            for (int i = 0; i < 4; i++) rp[i] = KPs[ty * 4 + i][k];
            float4 rv = *(const float4*)(&Vs[k][tx * 4]);
            #pragma unroll
            for (int i = 0; i < 4; i++) {
                o[i][0] = fmaf(rp[i], rv.x, o[i][0]);
                o[i][1] = fmaf(rp[i], rv.y, o[i][1]);
                o[i][2] = fmaf(rp[i], rv.z, o[i][2]);
                o[i][3] = fmaf(rp[i], rv.w, o[i][3]);
            }
        }
        __syncthreads();   // before next tile overwrites KPs/Vs
    }

    // write ctx
    #pragma unroll
    for (int i = 0; i < 4; i++) {
        float inv = 1.f / l[i];
        int r = qt * 64 + ty * 4 + i;
        float4 ov = make_float4(o[i][0] * inv, o[i][1] * inv,
                                o[i][2] * inv, o[i][3] * inv);
        *(float4*)(ctx + (size_t)b * SEQ * DMODEL + (size_t)r * DMODEL
                   + (size_t)h * HDIM + tx * 4) = ov;
    }
}

// ------------------------------ launch --------------------------------------
extern "C" void kernel_launch(void* const* d_in, const int* in_sizes, int n_in,
                              void* d_out, int out_size)
{
    const float* x   = (const float*)d_in[0];
    const float* Wq  = (const float*)d_in[1];
    const float* bq  = (const float*)d_in[2];
    const float* Wkd = (const float*)d_in[3];
    const float* bkd = (const float*)d_in[4];
    const float* Wvd = (const float*)d_in[5];
    const float* bvd = (const float*)d_in[6];
    const float* Wku = (const float*)d_in[7];
    const float* bku = (const float*)d_in[8];
    const float* Wvu = (const float*)d_in[9];
    const float* bvu = (const float*)d_in[10];
    const float* Wo  = (const float*)d_in[11];
    const float* bo  = (const float*)d_in[12];
    float* out = (float*)d_out;

    void *pQ, *pKL, *pVL, *pK, *pV, *pC;
    cudaGetSymbolAddress(&pQ,  g_Q);
    cudaGetSymbolAddress(&pKL, g_KL);
    cudaGetSymbolAddress(&pVL, g_VL);
    cudaGetSymbolAddress(&pK,  g_K);
    cudaGetSymbolAddress(&pV,  g_V);
    cudaGetSymbolAddress(&pC,  g_ctx);
    float* Qb  = (float*)pQ;
    float* KLb = (float*)pKL;
    float* VLb = (float*)pVL;
    float* Kb  = (float*)pK;
    float* Vb  = (float*)pV;
    float* Cb  = (float*)pC;

    dim3 thr(256);
    // projections
    sgemm_bias<<<dim3(DMODEL / BN, MROWS / BM), thr>>>(x, Wq,  bq,  Qb,  MROWS, DMODEL, DMODEL);
    sgemm_bias<<<dim3(LATENT / BN, MROWS / BM), thr>>>(x, Wkd, bkd, KLb, MROWS, LATENT, DMODEL);
    sgemm_bias<<<dim3(LATENT / BN, MROWS / BM), thr>>>(x, Wvd, bvd, VLb, MROWS, LATENT, DMODEL);
    sgemm_bias<<<dim3(DMODEL / BN, MROWS / BM), thr>>>(KLb, Wku, bku, Kb, MROWS, DMODEL, LATENT);
    sgemm_bias<<<dim3(DMODEL / BN, MROWS / BM), thr>>>(VLb, Wvu, bvu, Vb, MROWS, DMODEL, LATENT);
    // attention
    flash_attn<<<dim3(SEQ / 64, BATCH * NHEADS), thr>>>(Qb, Kb, Vb, Cb);
    // output projection
    sgemm_bias<<<dim3(DMODEL / BN, MROWS / BM), thr>>>(Cb, Wo, bo, out, MROWS, DMODEL, DMODEL);
}

// round 4
// speedup vs baseline: 1.4253x; 1.4253x over previous
#include <cuda_runtime.h>
#include <cuda_bf16.h>
#include <cstdint>
#include <cstddef>

// ---------------------------------------------------------------------------
// MLA attention, 3xTF32 mma.sync (split-precision HMMA).
//   B=2, S=2048, D_MODEL=1024, N_HEADS=16, HEAD_DIM=64, LATENT=256
// tcgen05 is unavailable (harness lowers via compute_103 family target), so
// we use mma.sync.m16n8k8.tf32 + ldmatrix. Single tf32 chains to ~3e-3 rel
// error (measured round 3); 3xTF32 (hi/lo split in registers) restores
// ~fp32 accuracy on every matmul stage except Q@K^T (error-insensitive,
// kept single-pass).
// ---------------------------------------------------------------------------

#define BATCH    2
#define SEQ      2048
#define DMODEL   1024
#define NHEADS   16
#define HDIM     64
#define LATENT   256
#define MROWS    (BATCH * SEQ)     // 4096

// ------------------------- scratch (device globals) ------------------------
__device__ float g_Q  [MROWS * DMODEL];
__device__ float g_KL [MROWS * LATENT];
__device__ float g_VL [MROWS * LATENT];
__device__ float g_K  [MROWS * DMODEL];
__device__ float g_V  [MROWS * DMODEL];
__device__ float g_ctx[MROWS * DMODEL];

// ----------------------------- helpers -------------------------------------
__device__ __forceinline__ uint32_t smem_u32(const void* p) {
    uint32_t a;
    asm("{ .reg .u64 t; cvta.to.shared.u64 t, %1; cvt.u32.u64 %0, t; }"
        : "=r"(a) : "l"(p));
    return a;
}

__device__ __forceinline__ void ldsm_x4(uint32_t* r, uint32_t addr) {
    asm volatile("ldmatrix.sync.aligned.m8n8.x4.shared.b16 {%0,%1,%2,%3}, [%4];"
                 : "=r"(r[0]), "=r"(r[1]), "=r"(r[2]), "=r"(r[3])
                 : "r"(addr) : "memory");
}

// D += A(16x8) * B(8x8), tf32 inputs, fp32 acc
__device__ __forceinline__ void mma_tf32(float* d, const uint32_t* a,
                                         uint32_t b0, uint32_t b1) {
    asm volatile(
        "mma.sync.aligned.m16n8k8.row.col.f32.tf32.tf32.f32 "
        "{%0,%1,%2,%3}, {%4,%5,%6,%7}, {%8,%9}, {%0,%1,%2,%3};"
        : "+f"(d[0]), "+f"(d[1]), "+f"(d[2]), "+f"(d[3])
        : "r"(a[0]), "r"(a[1]), "r"(a[2]), "r"(a[3]), "r"(b0), "r"(b1));
}

// split fp32 (raw bits) into tf32 hi + residual lo (hi = rna(tf32), lo exact)
__device__ __forceinline__ void tf32_split(uint32_t r, uint32_t& hi, uint32_t& lo) {
    float f = __uint_as_float(r);
    uint32_t h;
    asm("cvt.rna.tf32.f32 %0, %1;" : "=r"(h) : "f"(f));
    hi = h;
    lo = __float_as_uint(f - __uint_as_float(h));
}

// fast exp2 on the fma/alu pipes (B300 MUFU is slow: rt 8/SMSP).
// valid for x <= 0 (clamped at -100), rel err ~3e-6.
__device__ __forceinline__ float fexp2(float x) {
    x = fmaxf(x, -100.0f);
    int   i = __float2int_rn(x);
    float f = x - (float)i;                  // [-0.5, 0.5]
    float p =               1.3333558e-3f;
    p = fmaf(p, f, 9.6181291e-3f);
    p = fmaf(p, f, 5.5504109e-2f);
    p = fmaf(p, f, 2.4022651e-1f);
    p = fmaf(p, f, 6.9314718e-1f);
    p = fmaf(p, f, 1.0f);
    return __uint_as_float((uint32_t)((i + 127) << 23)) * p;
}

#define CP_ASYNC16(dst, src) \
    asm volatile("cp.async.cg.shared.global [%0], [%1], 16;" :: "r"(dst), "l"(src))
#define CP_COMMIT()  asm volatile("cp.async.commit_group;")
#define CP_WAIT0()   asm volatile("cp.async.wait_group 0;" ::: "memory")

// ------------------------------- 3xtf32 GEMM --------------------------------
// C[M,N] = A[M,K] @ B[K,N] + bias[N], row-major fp32.
// Tiles 128x128x32, 256 threads, 8 warps (warp tile 64m x 32n),
// double-buffered smem. A smem [m][k] 128B rows, B smem [n][k] 128B rows,
// XOR-swizzled; fragments via ldmatrix.x4(b16); hi/lo split in registers.
#define GSTAGE 32768                         // 16KB A + 16KB B per stage
__global__ __launch_bounds__(256) void gemm_mma(
    const float* __restrict__ A, const float* __restrict__ Bm,
    const float* __restrict__ bias, float* __restrict__ C,
    int M, int N, int K)
{
    extern __shared__ char smem[];
    const uint32_t sb = smem_u32(smem);

    const int tid = threadIdx.x;
    const int lid = tid & 31, wid = tid >> 5;
    const int bx = blockIdx.x, by = blockIdx.y;
    const int rr = lid & 7, mat1 = (lid >> 3) & 1, mat2 = lid >> 4;

    const float* Ab = A  + (size_t)by * 128 * K;
    const float* Bb = Bm + (size_t)bx * 128;

    const int Rm = (wid >> 2) * 64;          // warp row offset (0/64)
    const int Rn = (wid & 3) * 32;           // warp col offset (0..96)

    float acc[4][4][4];
    #pragma unroll
    for (int t = 0; t < 4; t++)
        #pragma unroll
        for (int j = 0; j < 4; j++)
            #pragma unroll
            for (int c = 0; c < 4; c++) acc[t][j][c] = 0.f;

    float4 breg[4];

    auto loadA_cp = [&](int k0, int s) {
        #pragma unroll
        for (int p = 0; p < 4; p++) {
            int f4 = tid + p * 256;
            int r  = f4 >> 3;
            int cb = (f4 & 7) << 4;
            uint32_t dst = sb + s * GSTAGE + r * 128 + (cb ^ ((r & 7) << 4));
            const float* src = Ab + (size_t)r * K + k0 + (cb >> 2);
            CP_ASYNC16(dst, src);
        }
        CP_COMMIT();
    };
    auto loadB_ldg = [&](int k0) {
        #pragma unroll
        for (int p = 0; p < 4; p++) {
            int idx = tid + p * 256;
            int n   = idx & 127;
            int kc  = (idx >> 7) << 2;
            const float* s0 = Bb + (size_t)(k0 + kc) * N + n;
            breg[p].x = s0[0];
            breg[p].y = s0[(size_t)N];
            breg[p].z = s0[(size_t)2 * N];
            breg[p].w = s0[(size_t)3 * N];
        }
    };
    auto storeB = [&](int s) {
        #pragma unroll
        for (int p = 0; p < 4; p++) {
            int idx = tid + p * 256;
            int n   = idx & 127;
            int cb  = (idx >> 7) << 4;
            *(float4*)(smem + s * GSTAGE + 16384 + n * 128 + (cb ^ ((n & 7) << 4)))
                = breg[p];
        }
    };

    loadA_cp(0, 0);
    loadB_ldg(0);
    CP_WAIT0();
    storeB(0);
    __syncthreads();

    const int nk = K >> 5;
    for (int i = 0; i < nk; i++) {
        const int s = i & 1;
        if (i + 1 < nk) {
            loadA_cp((i + 1) << 5, s ^ 1);
            loadB_ldg((i + 1) << 5);
        }
        const uint32_t aBase = sb + s * GSTAGE;
        const uint32_t bBase = aBase + 16384;

        #pragma unroll
        for (int ks = 0; ks < 4; ks++) {
            uint32_t ah[4][4], al[4][4];
            #pragma unroll
            for (int t = 0; t < 4; t++) {
                uint32_t af[4];
                int row = Rm + 16 * t + rr + (mat1 << 3);
                int cb  = ks * 32 + (mat2 << 4);
                ldsm_x4(af, aBase + row * 128 + (cb ^ ((row & 7) << 4)));
                #pragma unroll
                for (int e = 0; e < 4; e++) tf32_split(af[e], ah[t][e], al[t][e]);
            }
            uint32_t bh[2][4], bl[2][4];
            #pragma unroll
            for (int u = 0; u < 2; u++) {
                uint32_t bf[4];
                int row = Rn + 16 * u + rr + (mat2 << 3);
                int cb  = ks * 32 + (mat1 << 4);
                ldsm_x4(bf, bBase + row * 128 + (cb ^ ((row & 7) << 4)));
                #pragma unroll
                for (int e = 0; e < 4; e++) tf32_split(bf[e], bh[u][e], bl[u][e]);
            }
            #pragma unroll
            for (int t = 0; t < 4; t++)
                #pragma unroll
                for (int j = 0; j < 4; j++) {
                    const int u = j >> 1, v = (j & 1) * 2;
                    mma_tf32(acc[t][j], al[t], bh[u][v], bh[u][v + 1]);
                    mma_tf32(acc[t][j], ah[t], bl[u][v], bl[u][v + 1]);
                    mma_tf32(acc[t][j], ah[t], bh[u][v], bh[u][v + 1]);
                }
        }

        if (i + 1 < nk) {
            CP_WAIT0();
            storeB(s ^ 1);
        }
        __syncthreads();
    }

    const int g = lid >> 2, q = lid & 3;
    #pragma unroll
    for (int j = 0; j < 4; j++) {
        int col = bx * 128 + Rn + 8 * j + 2 * q;
        float b0 = bias[col], b1 = bias[col + 1];
        #pragma unroll
        for (int t = 0; t < 4; t++) {
            int row = by * 128 + Rm + 16 * t + g;
            *(float2*)(C + (size_t)row * N + col)
                = make_float2(acc[t][j][0] + b0, acc[t][j][1] + b1);
            *(float2*)(C + (size_t)(row + 8) * N + col)
                = make_float2(acc[t][j][2] + b0, acc[t][j][3] + b1);
        }
    }
}

// --------------------------- flash attention (mma) --------------------------
// grid (SEQ/128, BATCH*NHEADS), 256 threads = 8 warps, each warp owns 16 q-rows.
// smem: [0,32K) Q then P (128 rows x 256B), [32K,48K) K tile (64 x 256B),
//       [48K,64K) V^T tile (64 x 256B). XOR-swizzled.
// Q@K^T single tf32 (error-insensitive), P@V 3xtf32.
__global__ __launch_bounds__(256) void attn_mma(
    const float* __restrict__ Q, const float* __restrict__ K,
    const float* __restrict__ V, float* __restrict__ ctx)
{
    extern __shared__ char smem[];
    const uint32_t sb = smem_u32(smem);

    const int tid = threadIdx.x;
    const int lid = tid & 31, wid = tid >> 5;
    const int rr = lid & 7, mat1 = (lid >> 3) & 1, mat2 = lid >> 4;
    const int qt = blockIdx.x, bh = blockIdx.y;
    const int b = bh >> 4, h = bh & 15;

    const float qscale = 0.125f * 1.44269504f;   // scale * log2(e)
    const size_t tok0 = (size_t)b * SEQ;
    const float* Qg = Q + (tok0 + (size_t)qt * 128) * DMODEL + h * HDIM;
    const float* Kg = K + tok0 * DMODEL + h * HDIM;
    const float* Vg = V + tok0 * DMODEL + h * HDIM;

    #pragma unroll
    for (int p = 0; p < 8; p++) {
        int f4 = tid + p * 256;
        int r  = f4 >> 4;
        int cb = (f4 & 15) << 4;
        float4 v = *(const float4*)(Qg + (size_t)r * DMODEL + (cb >> 2));
        v.x *= qscale; v.y *= qscale; v.z *= qscale; v.w *= qscale;
        *(float4*)(smem + r * 256 + (cb ^ ((r & 7) << 4))) = v;
    }
    __syncthreads();

    uint32_t qf[8][4];
    {
        int row = wid * 16 + rr + (mat1 << 3);
        uint32_t base = sb + row * 256;
        int rsw = (row & 7) << 4;
        #pragma unroll
        for (int ks = 0; ks < 8; ks++) {
            int cb = ks * 32 + (mat2 << 4);
            ldsm_x4(qf[ks], base + (cb ^ rsw));
        }
    }

    float o[8][4];
    #pragma unroll
    for (int j = 0; j < 8; j++)
        #pragma unroll
        for (int c = 0; c < 4; c++) o[j][c] = 0.f;
    float m0 = -1e30f, m1 = -1e30f, l0 = 0.f, l1 = 0.f;

    for (int kt = 0; kt < SEQ / 64; kt++) {
        __syncthreads();
        #pragma unroll
        for (int p = 0; p < 4; p++) {
            int f4 = tid + p * 256;
            int r  = f4 >> 4;
            int cb = (f4 & 15) << 4;
            float4 v = *(const float4*)(Kg + (size_t)(kt * 64 + r) * DMODEL + (cb >> 2));
            *(float4*)(smem + 32768 + r * 256 + (cb ^ ((r & 7) << 4))) = v;
        }
        #pragma unroll
        for (int p = 0; p < 4; p++) {
            int idx = tid + p * 256;
            int hd  = idx >> 4;
            int kq  = (idx & 15) << 2;
            const float* s0 = Vg + (size_t)(kt * 64 + kq) * DMODEL + hd;
            float4 v;
            v.x = s0[0];
            v.y = s0[DMODEL];
            v.z = s0[2 * DMODEL];
            v.w = s0[3 * DMODEL];
            int cb = kq << 2;
            *(float4*)(smem + 49152 + hd * 256 + (cb ^ ((hd & 7) << 4))) = v;
        }
        __syncthreads();

        // S = Q @ K^T (single tf32; exp2 domain via qscale)
        float s[8][4];
        #pragma unroll
        for (int j = 0; j < 8; j++)
            #pragma unroll
            for (int c = 0; c < 4; c++) s[j][c] = 0.f;

        #pragma unroll
        for (int ks = 0; ks < 8; ks++) {
            uint32_t bf[4][4];
            #pragma unroll
            for (int u = 0; u < 4; u++) {
                int row = 16 * u + rr + (mat2 << 3);
                int cb  = ks * 32 + (mat1 << 4);
                ldsm_x4(bf[u], sb + 32768 + row * 256 + (cb ^ ((row & 7) << 4)));
            }
            #pragma unroll
            for (int j = 0; j < 8; j++)
                mma_tf32(s[j], qf[ks],
                         bf[j >> 1][(j & 1) * 2], bf[j >> 1][(j & 1) * 2 + 1]);
        }

        // online softmax
        float mx0 = -1e30f, mx1 = -1e30f;
        #pragma unroll
        for (int j = 0; j < 8; j++) {
            mx0 = fmaxf(mx0, fmaxf(s[j][0], s[j][1]));
            mx1 = fmaxf(mx1, fmaxf(s[j][2], s[j][3]));
        }
        mx0 = fmaxf(mx0, __shfl_xor_sync(0xffffffffu, mx0, 1));
        mx0 = fmaxf(mx0, __shfl_xor_sync(0xffffffffu, mx0, 2));
        mx1 = fmaxf(mx1, __shfl_xor_sync(0xffffffffu, mx1, 1));
        mx1 = fmaxf(mx1, __shfl_xor_sync(0xffffffffu, mx1, 2));
        float m0n = fmaxf(m0, mx0), m1n = fmaxf(m1, mx1);
        float a0 = fexp2(m0 - m0n), a1 = fexp2(m1 - m1n);
        m0 = m0n; m1 = m1n;

        float rs0 = 0.f, rs1 = 0.f;
        #pragma unroll
        for (int j = 0; j < 8; j++) {
            s[j][0] = fexp2(s[j][0] - m0n);
            s[j][1] = fexp2(s[j][1] - m0n);
            s[j][2] = fexp2(s[j][2] - m1n);
            s[j][3] = fexp2(s[j][3] - m1n);
            rs0 += s[j][0] + s[j][1];
            rs1 += s[j][2] + s[j][3];
            o[j][0] *= a0; o[j][1] *= a0;
            o[j][2] *= a1; o[j][3] *= a1;
        }
        rs0 += __shfl_xor_sync(0xffffffffu, rs0, 1);
        rs0 += __shfl_xor_sync(0xffffffffu, rs0, 2);
        rs1 += __shfl_xor_sync(0xffffffffu, rs1, 1);
        rs1 += __shfl_xor_sync(0xffffffffu, rs1, 2);
        l0 = l0 * a0 + rs0;
        l1 = l1 * a1 + rs1;

        // P -> smem (each warp writes only its own 16 rows)
        {
            int g = lid >> 2, q = lid & 3;
            int r0 = wid * 16 + g;
            int sw = (r0 & 7) << 4;
            #pragma unroll
            for (int j = 0; j < 8; j++) {
                int cb = (8 * j + 2 * q) << 2;
                *(float2*)(smem + r0 * 256 + (cb ^ sw))
                    = make_float2(s[j][0], s[j][1]);
                *(float2*)(smem + (r0 + 8) * 256 + (cb ^ sw))
                    = make_float2(s[j][2], s[j][3]);
            }
        }
        __syncwarp();

        // O += P @ V  (3xtf32)
        #pragma unroll
        for (int ks = 0; ks < 8; ks++) {
            uint32_t ah[4], al[4];
            {
                uint32_t af[4];
                int row = wid * 16 + rr + (mat1 << 3);
                int cb  = ks * 32 + (mat2 << 4);
                ldsm_x4(af, sb + row * 256 + (cb ^ ((row & 7) << 4)));
                #pragma unroll
                for (int e = 0; e < 4; e++) tf32_split(af[e], ah[e], al[e]);
            }
            uint32_t vh[4][4], vl[4][4];
            #pragma unroll
            for (int u = 0; u < 4; u++) {
                uint32_t bf[4];
                int row = 16 * u + rr + (mat2 << 3);
                int cb  = ks * 32 + (mat1 << 4);
                ldsm_x4(bf, sb + 49152 + row * 256 + (cb ^ ((row & 7) << 4)));
                #pragma unroll
                for (int e = 0; e < 4; e++) tf32_split(bf[e], vh[u][e], vl[u][e]);
            }
            #pragma unroll
            for (int j = 0; j < 8; j++) {
                const int u = j >> 1, v = (j & 1) * 2;
                mma_tf32(o[j], al, vh[u][v], vh[u][v + 1]);
                mma_tf32(o[j], ah, vl[u][v], vl[u][v + 1]);
                mma_tf32(o[j], ah, vh[u][v], vh[u][v + 1]);
            }
        }
    }

    const float inv0 = 1.f / l0, inv1 = 1.f / l1;
    const int g = lid >> 2, q = lid & 3;
    float* C0 = ctx + (tok0 + (size_t)qt * 128 + wid * 16 + g) * DMODEL + h * HDIM;
    float* C1 = C0 + (size_t)8 * DMODEL;
    #pragma unroll
    for (int j = 0; j < 8; j++) {
        int col = 8 * j + 2 * q;
        *(float2*)(C0 + col) = make_float2(o[j][0] * inv0, o[j][1] * inv0);
        *(float2*)(C1 + col) = make_float2(o[j][2] * inv1, o[j][3] * inv1);
    }
}

// ------------------------------ launch --------------------------------------
extern "C" void kernel_launch(void* const* d_in, const int* in_sizes, int n_in,
                              void* d_out, int out_size)
{
    const float* x   = (const float*)d_in[0];
    const float* Wq  = (const float*)d_in[1];
    const float* bq  = (const float*)d_in[2];
    const float* Wkd = (const float*)d_in[3];
    const float* bkd = (const float*)d_in[4];
    const float* Wvd = (const float*)d_in[5];
    const float* bvd = (const float*)d_in[6];
    const float* Wku = (const float*)d_in[7];
    const float* bku = (const float*)d_in[8];
    const float* Wvu = (const float*)d_in[9];
    const float* bvu = (const float*)d_in[10];
    const float* Wo  = (const float*)d_in[11];
    const float* bo  = (const float*)d_in[12];
    float* out = (float*)d_out;

    void *pQ, *pKL, *pVL, *pK, *pV, *pC;
    cudaGetSymbolAddress(&pQ,  g_Q);
    cudaGetSymbolAddress(&pKL, g_KL);
    cudaGetSymbolAddress(&pVL, g_VL);
    cudaGetSymbolAddress(&pK,  g_K);
    cudaGetSymbolAddress(&pV,  g_V);
    cudaGetSymbolAddress(&pC,  g_ctx);
    float* Qb  = (float*)pQ;
    float* KLb = (float*)pKL;
    float* VLb = (float*)pVL;
    float* Kb  = (float*)pK;
    float* Vb  = (float*)pV;
    float* Cb  = (float*)pC;

    cudaFuncSetAttribute(gemm_mma, cudaFuncAttributeMaxDynamicSharedMemorySize, 65536);
    cudaFuncSetAttribute(attn_mma, cudaFuncAttributeMaxDynamicSharedMemorySize, 65536);

    dim3 thr(256);
    gemm_mma<<<dim3(DMODEL / 128, MROWS / 128), thr, 65536>>>(x,   Wq,  bq,  Qb,  MROWS, DMODEL, DMODEL);
    gemm_mma<<<dim3(LATENT / 128, MROWS / 128), thr, 65536>>>(x,   Wkd, bkd, KLb, MROWS, LATENT, DMODEL);
    gemm_mma<<<dim3(LATENT / 128, MROWS / 128), thr, 65536>>>(x,   Wvd, bvd, VLb, MROWS, LATENT, DMODEL);
    gemm_mma<<<dim3(DMODEL / 128, MROWS / 128), thr, 65536>>>(KLb, Wku, bku, Kb,  MROWS, DMODEL, LATENT);
    gemm_mma<<<dim3(DMODEL / 128, MROWS / 128), thr, 65536>>>(VLb, Wvu, bvu, Vb,  MROWS, DMODEL, LATENT);
    attn_mma<<<dim3(SEQ / 128, BATCH * NHEADS), thr, 65536>>>(Qb, Kb, Vb, Cb);
    gemm_mma<<<dim3(DMODEL / 128, MROWS / 128), thr, 65536>>>(Cb,  Wo,  bo,  out, MROWS, DMODEL, DMODEL);
}

// round 5
// speedup vs baseline: 1.6291x; 1.1429x over previous
#include <cuda_runtime.h>
#include <cuda_bf16.h>
#include <cstdint>
#include <cstddef>

// ---------------------------------------------------------------------------
// MLA attention, 3xTF32 mma.sync (split-precision HMMA).
//   B=2, S=2048, D_MODEL=1024, N_HEADS=16, HEAD_DIM=64, LATENT=256
// Round 5: occupancy push. __launch_bounds__(256,2) (128 regs -> 2 CTAs/SM),
// z-batched paired GEMMs (fill the chip for the latent projections), and
// attention restructured so P has its own smem region (Q persists, fragments
// re-loaded per step -> fewer live registers).
// ---------------------------------------------------------------------------

#define BATCH    2
#define SEQ      2048
#define DMODEL   1024
#define NHEADS   16
#define HDIM     64
#define LATENT   256
#define MROWS    (BATCH * SEQ)     // 4096

// ------------------------- scratch (device globals) ------------------------
__device__ float g_Q  [MROWS * DMODEL];
__device__ float g_KL [MROWS * LATENT];
__device__ float g_VL [MROWS * LATENT];
__device__ float g_K  [MROWS * DMODEL];
__device__ float g_V  [MROWS * DMODEL];
__device__ float g_ctx[MROWS * DMODEL];

// ----------------------------- helpers -------------------------------------
__device__ __forceinline__ uint32_t smem_u32(const void* p) {
    uint32_t a;
    asm("{ .reg .u64 t; cvta.to.shared.u64 t, %1; cvt.u32.u64 %0, t; }"
        : "=r"(a) : "l"(p));
    return a;
}

__device__ __forceinline__ void ldsm_x4(uint32_t* r, uint32_t addr) {
    asm volatile("ldmatrix.sync.aligned.m8n8.x4.shared.b16 {%0,%1,%2,%3}, [%4];"
                 : "=r"(r[0]), "=r"(r[1]), "=r"(r[2]), "=r"(r[3])
                 : "r"(addr) : "memory");
}

// D += A(16x8) * B(8x8), tf32 inputs, fp32 acc
__device__ __forceinline__ void mma_tf32(float* d, const uint32_t* a,
                                         uint32_t b0, uint32_t b1) {
    asm volatile(
        "mma.sync.aligned.m16n8k8.row.col.f32.tf32.tf32.f32 "
        "{%0,%1,%2,%3}, {%4,%5,%6,%7}, {%8,%9}, {%0,%1,%2,%3};"
        : "+f"(d[0]), "+f"(d[1]), "+f"(d[2]), "+f"(d[3])
        : "r"(a[0]), "r"(a[1]), "r"(a[2]), "r"(a[3]), "r"(b0), "r"(b1));
}

// split fp32 (raw bits) into tf32 hi + residual lo
__device__ __forceinline__ void tf32_split(uint32_t r, uint32_t& hi, uint32_t& lo) {
    float f = __uint_as_float(r);
    uint32_t h;
    asm("cvt.rna.tf32.f32 %0, %1;" : "=r"(h) : "f"(f));
    hi = h;
    lo = __float_as_uint(f - __uint_as_float(h));
}

// fast exp2 on the fma/alu pipes (MUFU is slow on B300). x <= 0, clamped.
__device__ __forceinline__ float fexp2(float x) {
    x = fmaxf(x, -100.0f);
    int   i = __float2int_rn(x);
    float f = x - (float)i;
    float p =               1.3333558e-3f;
    p = fmaf(p, f, 9.6181291e-3f);
    p = fmaf(p, f, 5.5504109e-2f);
    p = fmaf(p, f, 2.4022651e-1f);
    p = fmaf(p, f, 6.9314718e-1f);
    p = fmaf(p, f, 1.0f);
    return __uint_as_float((uint32_t)((i + 127) << 23)) * p;
}

#define CP_ASYNC16(dst, src) \
    asm volatile("cp.async.cg.shared.global [%0], [%1], 16;" :: "r"(dst), "l"(src))
#define CP_COMMIT()  asm volatile("cp.async.commit_group;")
#define CP_WAIT0()   asm volatile("cp.async.wait_group 0;" ::: "memory")

// ------------------------------- 3xtf32 GEMM --------------------------------
// C[M,N] = A[M,K] @ B[K,N] + bias[N], row-major fp32.
// Tiles 128x128x32, 256 threads, 8 warps (warp tile 64m x 32n), double-buffered.
// blockIdx.z selects problem set {A,B,bias,C} vs {A2,B2,bias2,C2}.
#define GSTAGE 32768
__global__ __launch_bounds__(256, 2) void gemm_mma(
    const float* __restrict__ A, const float* __restrict__ Bm,
    const float* __restrict__ bias, float* __restrict__ C,
    const float* __restrict__ A2, const float* __restrict__ Bm2,
    const float* __restrict__ bias2, float* __restrict__ C2,
    int M, int N, int K)
{
    extern __shared__ char smem[];
    const uint32_t sb = smem_u32(smem);

    if (blockIdx.z) { A = A2; Bm = Bm2; bias = bias2; C = C2; }

    const int tid = threadIdx.x;
    const int lid = tid & 31, wid = tid >> 5;
    const int bx = blockIdx.x, by = blockIdx.y;
    const int rr = lid & 7, mat1 = (lid >> 3) & 1, mat2 = lid >> 4;

    const float* Ab = A  + (size_t)by * 128 * K;
    const float* Bb = Bm + (size_t)bx * 128;

    const int Rm = (wid >> 2) * 64;
    const int Rn = (wid & 3) * 32;

    float acc[4][4][4];
    #pragma unroll
    for (int t = 0; t < 4; t++)
        #pragma unroll
        for (int j = 0; j < 4; j++)
            #pragma unroll
            for (int c = 0; c < 4; c++) acc[t][j][c] = 0.f;

    float4 breg[4];

    auto loadA_cp = [&](int k0, int s) {
        #pragma unroll
        for (int p = 0; p < 4; p++) {
            int f4 = tid + p * 256;
            int r  = f4 >> 3;
            int cb = (f4 & 7) << 4;
            uint32_t dst = sb + s * GSTAGE + r * 128 + (cb ^ ((r & 7) << 4));
            const float* src = Ab + (size_t)r * K + k0 + (cb >> 2);
            CP_ASYNC16(dst, src);
        }
        CP_COMMIT();
    };
    auto loadB_ldg = [&](int k0) {
        #pragma unroll
        for (int p = 0; p < 4; p++) {
            int idx = tid + p * 256;
            int n   = idx & 127;
            int kc  = (idx >> 7) << 2;
            const float* s0 = Bb + (size_t)(k0 + kc) * N + n;
            breg[p].x = s0[0];
            breg[p].y = s0[(size_t)N];
            breg[p].z = s0[(size_t)2 * N];
            breg[p].w = s0[(size_t)3 * N];
        }
    };
    auto storeB = [&](int s) {
        #pragma unroll
        for (int p = 0; p < 4; p++) {
            int idx = tid + p * 256;
            int n   = idx & 127;
            int cb  = (idx >> 7) << 4;
            *(float4*)(smem + s * GSTAGE + 16384 + n * 128 + (cb ^ ((n & 7) << 4)))
                = breg[p];
        }
    };

    loadA_cp(0, 0);
    loadB_ldg(0);
    CP_WAIT0();
    storeB(0);
    __syncthreads();

    const int nk = K >> 5;
    for (int i = 0; i < nk; i++) {
        const int s = i & 1;
        if (i + 1 < nk) {
            loadA_cp((i + 1) << 5, s ^ 1);
            loadB_ldg((i + 1) << 5);
        }
        const uint32_t aBase = sb + s * GSTAGE;
        const uint32_t bBase = aBase + 16384;

        #pragma unroll
        for (int ks = 0; ks < 4; ks++) {
            uint32_t ah[4][4], al[4][4];
            #pragma unroll
            for (int t = 0; t < 4; t++) {
                uint32_t af[4];
                int row = Rm + 16 * t + rr + (mat1 << 3);
                int cb  = ks * 32 + (mat2 << 4);
                ldsm_x4(af, aBase + row * 128 + (cb ^ ((row & 7) << 4)));
                #pragma unroll
                for (int e = 0; e < 4; e++) tf32_split(af[e], ah[t][e], al[t][e]);
            }
            uint32_t bh[2][4], bl[2][4];
            #pragma unroll
            for (int u = 0; u < 2; u++) {
                uint32_t bf[4];
                int row = Rn + 16 * u + rr + (mat2 << 3);
                int cb  = ks * 32 + (mat1 << 4);
                ldsm_x4(bf, bBase + row * 128 + (cb ^ ((row & 7) << 4)));
                #pragma unroll
                for (int e = 0; e < 4; e++) tf32_split(bf[e], bh[u][e], bl[u][e]);
            }
            #pragma unroll
            for (int t = 0; t < 4; t++)
                #pragma unroll
                for (int j = 0; j < 4; j++) {
                    const int u = j >> 1, v = (j & 1) * 2;
                    mma_tf32(acc[t][j], al[t], bh[u][v], bh[u][v + 1]);
                    mma_tf32(acc[t][j], ah[t], bl[u][v], bl[u][v + 1]);
                    mma_tf32(acc[t][j], ah[t], bh[u][v], bh[u][v + 1]);
                }
        }

        if (i + 1 < nk) {
            CP_WAIT0();
            storeB(s ^ 1);
        }
        __syncthreads();
    }

    const int g = lid >> 2, q = lid & 3;
    #pragma unroll
    for (int j = 0; j < 4; j++) {
        int col = bx * 128 + Rn + 8 * j + 2 * q;
        float b0 = bias[col], b1 = bias[col + 1];
        #pragma unroll
        for (int t = 0; t < 4; t++) {
            int row = by * 128 + Rm + 16 * t + g;
            *(float2*)(C + (size_t)row * N + col)
                = make_float2(acc[t][j][0] + b0, acc[t][j][1] + b1);
            *(float2*)(C + (size_t)(row + 8) * N + col)
                = make_float2(acc[t][j][2] + b0, acc[t][j][3] + b1);
        }
    }
}

// --------------------------- flash attention (mma) --------------------------
// grid (SEQ/128, BATCH*NHEADS), 256 threads = 8 warps, warp owns 16 q-rows.
// smem: Q [0,32K), P [32K,64K), K [64K,80K), V^T [80K,96K). XOR-swizzled.
// Q@K^T single tf32, P@V 3xtf32. Q persists in smem; fragments reloaded.
#define ATTN_SMEM 98304
#define POFF 32768
#define KOFF 65536
#define VOFF 81920
__global__ __launch_bounds__(256, 2) void attn_mma(
    const float* __restrict__ Q, const float* __restrict__ K,
    const float* __restrict__ V, float* __restrict__ ctx)
{
    extern __shared__ char smem[];
    const uint32_t sb = smem_u32(smem);

    const int tid = threadIdx.x;
    const int lid = tid & 31, wid = tid >> 5;
    const int rr = lid & 7, mat1 = (lid >> 3) & 1, mat2 = lid >> 4;
    const int qt = blockIdx.x, bh = blockIdx.y;
    const int b = bh >> 4, h = bh & 15;

    const float qscale = 0.125f * 1.44269504f;   // scale * log2(e)
    const size_t tok0 = (size_t)b * SEQ;
    const float* Qg = Q + (tok0 + (size_t)qt * 128) * DMODEL + h * HDIM;
    const float* Kg = K + tok0 * DMODEL + h * HDIM;
    const float* Vg = V + tok0 * DMODEL + h * HDIM;

    // Q (pre-scaled) -> smem, persists for the whole kernel
    #pragma unroll
    for (int p = 0; p < 8; p++) {
        int f4 = tid + p * 256;
        int r  = f4 >> 4;
        int cb = (f4 & 15) << 4;
        float4 v = *(const float4*)(Qg + (size_t)r * DMODEL + (cb >> 2));
        v.x *= qscale; v.y *= qscale; v.z *= qscale; v.w *= qscale;
        *(float4*)(smem + r * 256 + (cb ^ ((r & 7) << 4))) = v;
    }

    float o[8][4];
    #pragma unroll
    for (int j = 0; j < 8; j++)
        #pragma unroll
        for (int c = 0; c < 4; c++) o[j][c] = 0.f;
    float m0 = -1e30f, m1 = -1e30f, l0 = 0.f, l1 = 0.f;

    const int qrow = wid * 16 + rr + (mat1 << 3);
    const int qsw  = (qrow & 7) << 4;

    __syncthreads();

    for (int kt = 0; kt < SEQ / 64; kt++) {
        if (kt) __syncthreads();   // prior PV reads of V^T done before overwrite
        // K tile [key][hd]
        #pragma unroll
        for (int p = 0; p < 4; p++) {
            int f4 = tid + p * 256;
            int r  = f4 >> 4;
            int cb = (f4 & 15) << 4;
            float4 v = *(const float4*)(Kg + (size_t)(kt * 64 + r) * DMODEL + (cb >> 2));
            *(float4*)(smem + KOFF + r * 256 + (cb ^ ((r & 7) << 4))) = v;
        }
        // V^T tile [hd][key]
        #pragma unroll
        for (int p = 0; p < 4; p++) {
            int idx = tid + p * 256;
            int hd  = idx >> 4;
            int kq  = (idx & 15) << 2;
            const float* s0 = Vg + (size_t)(kt * 64 + kq) * DMODEL + hd;
            float4 v;
            v.x = s0[0];
            v.y = s0[DMODEL];
            v.z = s0[2 * DMODEL];
            v.w = s0[3 * DMODEL];
            int cb = kq << 2;
            *(float4*)(smem + VOFF + hd * 256 + (cb ^ ((hd & 7) << 4))) = v;
        }
        __syncthreads();

        // S = Q @ K^T (single tf32; exp2 domain)
        float s[8][4];
        #pragma unroll
        for (int j = 0; j < 8; j++)
            #pragma unroll
            for (int c = 0; c < 4; c++) s[j][c] = 0.f;

        #pragma unroll
        for (int ks = 0; ks < 8; ks++) {
            uint32_t qf[4];
            ldsm_x4(qf, sb + qrow * 256 + ((ks * 32 + (mat2 << 4)) ^ qsw));
            uint32_t bf[4][4];
            #pragma unroll
            for (int u = 0; u < 4; u++) {
                int row = 16 * u + rr + (mat2 << 3);
                int cb  = ks * 32 + (mat1 << 4);
                ldsm_x4(bf[u], sb + KOFF + row * 256 + (cb ^ ((row & 7) << 4)));
            }
            #pragma unroll
            for (int j = 0; j < 8; j++)
                mma_tf32(s[j], qf,
                         bf[j >> 1][(j & 1) * 2], bf[j >> 1][(j & 1) * 2 + 1]);
        }

        // online softmax
        float mx0 = -1e30f, mx1 = -1e30f;
        #pragma unroll
        for (int j = 0; j < 8; j++) {
            mx0 = fmaxf(mx0, fmaxf(s[j][0], s[j][1]));
            mx1 = fmaxf(mx1, fmaxf(s[j][2], s[j][3]));
        }
        mx0 = fmaxf(mx0, __shfl_xor_sync(0xffffffffu, mx0, 1));
        mx0 = fmaxf(mx0, __shfl_xor_sync(0xffffffffu, mx0, 2));
        mx1 = fmaxf(mx1, __shfl_xor_sync(0xffffffffu, mx1, 1));
        mx1 = fmaxf(mx1, __shfl_xor_sync(0xffffffffu, mx1, 2));
        float m0n = fmaxf(m0, mx0), m1n = fmaxf(m1, mx1);
        float a0 = fexp2(m0 - m0n), a1 = fexp2(m1 - m1n);
        m0 = m0n; m1 = m1n;

        float rs0 = 0.f, rs1 = 0.f;
        #pragma unroll
        for (int j = 0; j < 8; j++) {
            s[j][0] = fexp2(s[j][0] - m0n);
            s[j][1] = fexp2(s[j][1] - m0n);
            s[j][2] = fexp2(s[j][2] - m1n);
            s[j][3] = fexp2(s[j][3] - m1n);
            rs0 += s[j][0] + s[j][1];
            rs1 += s[j][2] + s[j][3];
            o[j][0] *= a0; o[j][1] *= a0;
            o[j][2] *= a1; o[j][3] *= a1;
        }
        rs0 += __shfl_xor_sync(0xffffffffu, rs0, 1);
        rs0 += __shfl_xor_sync(0xffffffffu, rs0, 2);
        rs1 += __shfl_xor_sync(0xffffffffu, rs1, 1);
        rs1 += __shfl_xor_sync(0xffffffffu, rs1, 2);
        l0 = l0 * a0 + rs0;
        l1 = l1 * a1 + rs1;

        // P -> smem (own region; warp-private rows)
        {
            int g = lid >> 2, q = lid & 3;
            int r0 = wid * 16 + g;
            int sw = (r0 & 7) << 4;
            #pragma unroll
            for (int j = 0; j < 8; j++) {
                int cb = (8 * j + 2 * q) << 2;
                *(float2*)(smem + POFF + r0 * 256 + (cb ^ sw))
                    = make_float2(s[j][0], s[j][1]);
                *(float2*)(smem + POFF + (r0 + 8) * 256 + (cb ^ sw))
                    = make_float2(s[j][2], s[j][3]);
            }
        }
        __syncwarp();

        // O += P @ V (3xtf32)
        #pragma unroll
        for (int ks = 0; ks < 8; ks++) {
            uint32_t ah[4], al[4];
            {
                uint32_t af[4];
                int cb = ks * 32 + (mat2 << 4);
                ldsm_x4(af, sb + POFF + qrow * 256 + (cb ^ qsw));
                #pragma unroll
                for (int e = 0; e < 4; e++) tf32_split(af[e], ah[e], al[e]);
            }
            uint32_t vh[4][4], vl[4][4];
            #pragma unroll
            for (int u = 0; u < 4; u++) {
                uint32_t bf[4];
                int row = 16 * u + rr + (mat2 << 3);
                int cb  = ks * 32 + (mat1 << 4);
                ldsm_x4(bf, sb + VOFF + row * 256 + (cb ^ ((row & 7) << 4)));
                #pragma unroll
                for (int e = 0; e < 4; e++) tf32_split(bf[e], vh[u][e], vl[u][e]);
            }
            #pragma unroll
            for (int j = 0; j < 8; j++) {
                const int u = j >> 1, v = (j & 1) * 2;
                mma_tf32(o[j], al, vh[u][v], vh[u][v + 1]);
                mma_tf32(o[j], ah, vl[u][v], vl[u][v + 1]);
                mma_tf32(o[j], ah, vh[u][v], vh[u][v + 1]);
            }
        }
    }

    const float inv0 = 1.f / l0, inv1 = 1.f / l1;
    const int g = lid >> 2, q = lid & 3;
    float* C0 = ctx + (tok0 + (size_t)qt * 128 + wid * 16 + g) * DMODEL + h * HDIM;
    float* C1 = C0 + (size_t)8 * DMODEL;
    #pragma unroll
    for (int j = 0; j < 8; j++) {
        int col = 8 * j + 2 * q;
        *(float2*)(C0 + col) = make_float2(o[j][0] * inv0, o[j][1] * inv0);
        *(float2*)(C1 + col) = make_float2(o[j][2] * inv1, o[j][3] * inv1);
    }
}

// ------------------------------ launch --------------------------------------
extern "C" void kernel_launch(void* const* d_in, const int* in_sizes, int n_in,
                              void* d_out, int out_size)
{
    const float* x   = (const float*)d_in[0];
    const float* Wq  = (const float*)d_in[1];
    const float* bq  = (const float*)d_in[2];
    const float* Wkd = (const float*)d_in[3];
    const float* bkd = (const float*)d_in[4];
    const float* Wvd = (const float*)d_in[5];
    const float* bvd = (const float*)d_in[6];
    const float* Wku = (const float*)d_in[7];
    const float* bku = (const float*)d_in[8];
    const float* Wvu = (const float*)d_in[9];
    const float* bvu = (const float*)d_in[10];
    const float* Wo  = (const float*)d_in[11];
    const float* bo  = (const float*)d_in[12];
    float* out = (float*)d_out;

    void *pQ, *pKL, *pVL, *pK, *pV, *pC;
    cudaGetSymbolAddress(&pQ,  g_Q);
    cudaGetSymbolAddress(&pKL, g_KL);
    cudaGetSymbolAddress(&pVL, g_VL);
    cudaGetSymbolAddress(&pK,  g_K);
    cudaGetSymbolAddress(&pV,  g_V);
    cudaGetSymbolAddress(&pC,  g_ctx);
    float* Qb  = (float*)pQ;
    float* KLb = (float*)pKL;
    float* VLb = (float*)pVL;
    float* Kb  = (float*)pK;
    float* Vb  = (float*)pV;
    float* Cb  = (float*)pC;

    cudaFuncSetAttribute(gemm_mma, cudaFuncAttributeMaxDynamicSharedMemorySize, 65536);
    cudaFuncSetAttribute(attn_mma, cudaFuncAttributeMaxDynamicSharedMemorySize, ATTN_SMEM);

    dim3 thr(256);
    // Q projection
    gemm_mma<<<dim3(DMODEL / 128, MROWS / 128, 1), thr, 65536>>>(
        x, Wq, bq, Qb,  x, Wq, bq, Qb,  MROWS, DMODEL, DMODEL);
    // latent down-projections, batched (z=2) -> 128 CTAs
    gemm_mma<<<dim3(LATENT / 128, MROWS / 128, 2), thr, 65536>>>(
        x, Wkd, bkd, KLb,  x, Wvd, bvd, VLb,  MROWS, LATENT, DMODEL);
    // up-projections, batched (z=2) -> 512 CTAs
    gemm_mma<<<dim3(DMODEL / 128, MROWS / 128, 2), thr, 65536>>>(
        KLb, Wku, bku, Kb,  VLb, Wvu, bvu, Vb,  MROWS, DMODEL, LATENT);
    // attention
    attn_mma<<<dim3(SEQ / 128, BATCH * NHEADS), thr, ATTN_SMEM>>>(Qb, Kb, Vb, Cb);
    // output projection
    gemm_mma<<<dim3(DMODEL / 128, MROWS / 128, 1), thr, 65536>>>(
        Cb, Wo, bo, out,  Cb, Wo, bo, out,  MROWS, DMODEL, DMODEL);
}

// round 6
// speedup vs baseline: 2.6052x; 1.5992x over previous
#include <cuda_runtime.h>
#include <cuda_bf16.h>
#include <cstdint>
#include <cstddef>

// ---------------------------------------------------------------------------
// MLA attention, 3-term bf16 split-precision mma.sync (m16n8k16).
//   B=2, S=2048, D_MODEL=1024, N_HEADS=16, HEAD_DIM=64, LATENT=256
// Every operand f = hi + lo with hi,lo bf16 (~17 mantissa bits combined);
// D += ah*bh + al*bh + ah*bl on the tensor pipe (fp32 accum).
// hi/lo are stored as separate bf16 smem planes (conversion hoisted into the
// tile loaders), so fragments come from native b16 ldmatrix with no per-use
// splitting. Attention keeps P entirely in registers (acc layout == A-frag
// layout for bf16 k16).
// ---------------------------------------------------------------------------

#define BATCH    2
#define SEQ      2048
#define DMODEL   1024
#define NHEADS   16
#define HDIM     64
#define LATENT   256
#define MROWS    (BATCH * SEQ)     // 4096

// ------------------------- scratch (device globals) ------------------------
__device__ float g_Q  [MROWS * DMODEL];
__device__ float g_KL [MROWS * LATENT];
__device__ float g_VL [MROWS * LATENT];
__device__ float g_K  [MROWS * DMODEL];
__device__ float g_V  [MROWS * DMODEL];
__device__ float g_ctx[MROWS * DMODEL];

// ----------------------------- helpers -------------------------------------
__device__ __forceinline__ uint32_t smem_u32(const void* p) {
    uint32_t a;
    asm("{ .reg .u64 t; cvta.to.shared.u64 t, %1; cvt.u32.u64 %0, t; }"
        : "=r"(a) : "l"(p));
    return a;
}

__device__ __forceinline__ void ldsm_x4(uint32_t* r, uint32_t addr) {
    asm volatile("ldmatrix.sync.aligned.m8n8.x4.shared.b16 {%0,%1,%2,%3}, [%4];"
                 : "=r"(r[0]), "=r"(r[1]), "=r"(r[2]), "=r"(r[3])
                 : "r"(addr) : "memory");
}

// D += A(16x16) * B(16x8), bf16 inputs, fp32 acc
__device__ __forceinline__ void mma_bf16(float* d, const uint32_t* a,
                                         uint32_t b0, uint32_t b1) {
    asm volatile(
        "mma.sync.aligned.m16n8k16.row.col.f32.bf16.bf16.f32 "
        "{%0,%1,%2,%3}, {%4,%5,%6,%7}, {%8,%9}, {%0,%1,%2,%3};"
        : "+f"(d[0]), "+f"(d[1]), "+f"(d[2]), "+f"(d[3])
        : "r"(a[0]), "r"(a[1]), "r"(a[2]), "r"(a[3]), "r"(b0), "r"(b1));
}

// (f0,f1) -> packed bf16x2 hi and lo (lo = exact residual, bf16-rounded)
__device__ __forceinline__ void cvt_pair(float f0, float f1,
                                         uint32_t& hi, uint32_t& lo) {
    __nv_bfloat162 h = __floats2bfloat162_rn(f0, f1);
    uint32_t u = *reinterpret_cast<uint32_t*>(&h);
    float h0 = __uint_as_float(u << 16);
    float h1 = __uint_as_float(u & 0xffff0000u);
    __nv_bfloat162 l = __floats2bfloat162_rn(f0 - h0, f1 - h1);
    hi = u;
    lo = *reinterpret_cast<uint32_t*>(&l);
}

// fast exp2 on the fma/alu pipes (MUFU is slow on B300). x <= 0, clamped.
__device__ __forceinline__ float fexp2(float x) {
    x = fmaxf(x, -100.0f);
    int   i = __float2int_rn(x);
    float f = x - (float)i;
    float p =               1.3333558e-3f;
    p = fmaf(p, f, 9.6181291e-3f);
    p = fmaf(p, f, 5.5504109e-2f);
    p = fmaf(p, f, 2.4022651e-1f);
    p = fmaf(p, f, 6.9314718e-1f);
    p = fmaf(p, f, 1.0f);
    return __uint_as_float((uint32_t)((i + 127) << 23)) * p;
}

// ------------------------------ bf16x3 GEMM ---------------------------------
// C[M,N] = A[M,K] @ B[K,N] + bias[N], row-major fp32 in/out.
// Tiles 128x128x32, 256 threads, 8 warps (warp tile 64m x 32n), double-buffered
// bf16 hi/lo planes (pitch 80B per 32-elem row -> conflict-free, no swizzle).
// Stage layout: Ahi +0, Alo +10240, Bhi +20480, Blo +30720 (stride 40960).
#define GP     80                    // plane pitch (bytes) for 32 bf16 per row
#define GPLANE 10240                 // 128 rows * 80
#define GSTG   40960
#define GEMM_SMEM (2 * GSTG)
__global__ __launch_bounds__(256, 2) void gemm_mma(
    const float* __restrict__ A, const float* __restrict__ Bm,
    const float* __restrict__ bias, float* __restrict__ C,
    const float* __restrict__ A2, const float* __restrict__ Bm2,
    const float* __restrict__ bias2, float* __restrict__ C2,
    int M, int N, int K)
{
    extern __shared__ char smem[];
    const uint32_t sb = smem_u32(smem);

    if (blockIdx.z) { A = A2; Bm = Bm2; bias = bias2; C = C2; }

    const int tid = threadIdx.x;
    const int lid = tid & 31, wid = tid >> 5;
    const int bx = blockIdx.x, by = blockIdx.y;
    const int rr = lid & 7, mat1 = (lid >> 3) & 1, mat2 = lid >> 4;

    const float* Ab = A  + (size_t)by * 128 * K;
    const float* Bb = Bm + (size_t)bx * 128;

    const int Rm = (wid >> 2) * 64;
    const int Rn = (wid & 3) * 32;

    float acc[4][4][4];
    #pragma unroll
    for (int t = 0; t < 4; t++)
        #pragma unroll
        for (int j = 0; j < 4; j++)
            #pragma unroll
            for (int c = 0; c < 4; c++) acc[t][j][c] = 0.f;

    uint32_t ah8[8], al8[8], bh8[8], bl8[8];   // staging (converted pairs)

    auto ldgA = [&](int k0) {
        #pragma unroll
        for (int p = 0; p < 4; p++) {
            int f4 = tid + p * 256;
            int r  = f4 >> 3;                 // 0..127
            int c4 = (f4 & 7) << 2;           // 0,4,..28
            float4 v = *(const float4*)(Ab + (size_t)r * K + k0 + c4);
            cvt_pair(v.x, v.y, ah8[2 * p],     al8[2 * p]);
            cvt_pair(v.z, v.w, ah8[2 * p + 1], al8[2 * p + 1]);
        }
    };
    auto ldgB = [&](int k0) {
        #pragma unroll
        for (int p = 0; p < 4; p++) {
            int idx = tid + p * 256;
            int n   = idx & 127;
            int kc  = (idx >> 7) << 2;        // 0,4,..28
            const float* s0 = Bb + (size_t)(k0 + kc) * N + n;
            float v0 = s0[0];
            float v1 = s0[(size_t)N];
            float v2 = s0[(size_t)2 * N];
            float v3 = s0[(size_t)3 * N];
            cvt_pair(v0, v1, bh8[2 * p],     bl8[2 * p]);
            cvt_pair(v2, v3, bh8[2 * p + 1], bl8[2 * p + 1]);
        }
    };
    auto stsAB = [&](int s) {
        char* stg = smem + s * GSTG;
        #pragma unroll
        for (int p = 0; p < 4; p++) {
            int f4 = tid + p * 256;
            int r  = f4 >> 3;
            int c4 = (f4 & 7) << 2;
            char* a0 = stg + r * GP + c4 * 2;
            *(uint2*)(a0)          = make_uint2(ah8[2 * p], ah8[2 * p + 1]);
            *(uint2*)(a0 + GPLANE) = make_uint2(al8[2 * p], al8[2 * p + 1]);
        }
        #pragma unroll
        for (int p = 0; p < 4; p++) {
            int idx = tid + p * 256;
            int n   = idx & 127;
            int kc  = (idx >> 7) << 2;
            char* b0 = stg + 2 * GPLANE + n * GP + kc * 2;
            *(uint2*)(b0)          = make_uint2(bh8[2 * p], bh8[2 * p + 1]);
            *(uint2*)(b0 + GPLANE) = make_uint2(bl8[2 * p], bl8[2 * p + 1]);
        }
    };

    // prologue
    ldgA(0); ldgB(0); stsAB(0);
    __syncthreads();

    const int nk = K >> 5;
    for (int i = 0; i < nk; i++) {
        const int s = i & 1;
        if (i + 1 < nk) {
            ldgA((i + 1) << 5);
            ldgB((i + 1) << 5);
            stsAB(s ^ 1);      // other-stage planes are free (prev-iter sync)
        }
        const uint32_t aBase = sb + s * GSTG;
        const uint32_t bBase = aBase + 2 * GPLANE;

        #pragma unroll
        for (int ks = 0; ks < 2; ks++) {       // two k16 steps per k32 tile
            uint32_t bh[2][4], bl[2][4];
            #pragma unroll
            for (int u = 0; u < 2; u++) {
                int row = Rn + 16 * u + rr + (mat2 << 3);
                int cb  = ks * 32 + mat1 * 16;
                ldsm_x4(bh[u], bBase + row * GP + cb);
                ldsm_x4(bl[u], bBase + GPLANE + row * GP + cb);
            }
            #pragma unroll
            for (int t = 0; t < 4; t++) {
                uint32_t ah[4], al[4];
                int row = Rm + 16 * t + rr + (mat1 << 3);
                int cb  = ks * 32 + mat2 * 16;
                ldsm_x4(ah, aBase + row * GP + cb);
                ldsm_x4(al, aBase + GPLANE + row * GP + cb);
                #pragma unroll
                for (int j = 0; j < 4; j++) {
                    const int u = j >> 1, v = (j & 1) * 2;
                    mma_bf16(acc[t][j], al, bh[u][v], bh[u][v + 1]);
                    mma_bf16(acc[t][j], ah, bl[u][v], bl[u][v + 1]);
                    mma_bf16(acc[t][j], ah, bh[u][v], bh[u][v + 1]);
                }
            }
        }
        __syncthreads();
    }

    const int g = lid >> 2, q = lid & 3;
    #pragma unroll
    for (int j = 0; j < 4; j++) {
        int col = bx * 128 + Rn + 8 * j + 2 * q;
        float b0 = bias[col], b1 = bias[col + 1];
        #pragma unroll
        for (int t = 0; t < 4; t++) {
            int row = by * 128 + Rm + 16 * t + g;
            *(float2*)(C + (size_t)row * N + col)
                = make_float2(acc[t][j][0] + b0, acc[t][j][1] + b1);
            *(float2*)(C + (size_t)(row + 8) * N + col)
                = make_float2(acc[t][j][2] + b0, acc[t][j][3] + b1);
        }
    }
}

// --------------------------- flash attention (mma) --------------------------
// grid (SEQ/128, BATCH*NHEADS), 256 threads = 8 warps, warp owns 16 q-rows.
// bf16 hi/lo planes, pitch 144B per 64-elem row (conflict-free, no swizzle):
//   Qhi 0, Qlo 18432, Khi 36864, Klo 46080, Vhi 55296, Vlo 64512 (total 73728).
// P stays in registers: bf16 acc layout == m16n8k16 A-frag layout.
#define AP     144
#define QHI    0
#define QLO    18432
#define KHI    36864
#define KLO    46080
#define VHI    55296
#define VLO    64512
#define ATTN_SMEM 73728
__global__ __launch_bounds__(256, 2) void attn_mma(
    const float* __restrict__ Q, const float* __restrict__ K,
    const float* __restrict__ V, float* __restrict__ ctx)
{
    extern __shared__ char smem[];
    const uint32_t sb = smem_u32(smem);

    const int tid = threadIdx.x;
    const int lid = tid & 31, wid = tid >> 5;
    const int rr = lid & 7, mat1 = (lid >> 3) & 1, mat2 = lid >> 4;
    const int qt = blockIdx.x, bh_ = blockIdx.y;
    const int b = bh_ >> 4, h = bh_ & 15;

    const float qscale = 0.125f * 1.44269504f;   // scale * log2(e)
    const size_t tok0 = (size_t)b * SEQ;
    const float* Qg = Q + (tok0 + (size_t)qt * 128) * DMODEL + h * HDIM;
    const float* Kg = K + tok0 * DMODEL + h * HDIM;
    const float* Vg = V + tok0 * DMODEL + h * HDIM;

    // Q (pre-scaled) -> bf16 planes, persists
    #pragma unroll
    for (int p = 0; p < 8; p++) {
        int f4 = tid + p * 256;
        int r  = f4 >> 4;
        int c4 = (f4 & 15) << 2;
        float4 v = *(const float4*)(Qg + (size_t)r * DMODEL + c4);
        uint32_t h0, l0, h1, l1;
        cvt_pair(v.x * qscale, v.y * qscale, h0, l0);
        cvt_pair(v.z * qscale, v.w * qscale, h1, l1);
        char* a0 = smem + QHI + r * AP + c4 * 2;
        *(uint2*)(a0)               = make_uint2(h0, h1);
        *(uint2*)(a0 + (QLO - QHI)) = make_uint2(l0, l1);
    }

    float o[8][4];
    #pragma unroll
    for (int j = 0; j < 8; j++)
        #pragma unroll
        for (int c = 0; c < 4; c++) o[j][c] = 0.f;
    float m0 = -1e30f, m1 = -1e30f, l0s = 0.f, l1s = 0.f;

    const int qrow = wid * 16 + rr + (mat1 << 3);

    __syncthreads();

    for (int kt = 0; kt < SEQ / 64; kt++) {
        if (kt) __syncthreads();   // prior QK/PV reads done before overwrite
        // K tile [key][hd] -> planes
        #pragma unroll
        for (int p = 0; p < 4; p++) {
            int f4 = tid + p * 256;
            int r  = f4 >> 4;                  // 0..63
            int c4 = (f4 & 15) << 2;
            float4 v = *(const float4*)(Kg + (size_t)(kt * 64 + r) * DMODEL + c4);
            uint32_t h0, l0, h1, l1;
            cvt_pair(v.x, v.y, h0, l0);
            cvt_pair(v.z, v.w, h1, l1);
            char* a0 = smem + KHI + r * AP + c4 * 2;
            *(uint2*)(a0)               = make_uint2(h0, h1);
            *(uint2*)(a0 + (KLO - KHI)) = make_uint2(l0, l1);
        }
        // V^T tile [hd][key] -> planes (transpose gather)
        #pragma unroll
        for (int p = 0; p < 4; p++) {
            int idx = tid + p * 256;
            int hd  = idx >> 4;
            int kq  = (idx & 15) << 2;
            const float* s0 = Vg + (size_t)(kt * 64 + kq) * DMODEL + hd;
            float v0 = s0[0];
            float v1 = s0[DMODEL];
            float v2 = s0[2 * DMODEL];
            float v3 = s0[3 * DMODEL];
            uint32_t h0, l0, h1, l1;
            cvt_pair(v0, v1, h0, l0);
            cvt_pair(v2, v3, h1, l1);
            char* a0 = smem + VHI + hd * AP + kq * 2;
            *(uint2*)(a0)               = make_uint2(h0, h1);
            *(uint2*)(a0 + (VLO - VHI)) = make_uint2(l0, l1);
        }
        __syncthreads();

        // S = Q @ K^T (3-term bf16; exp2 domain via qscale)
        float s[8][4];
        #pragma unroll
        for (int j = 0; j < 8; j++)
            #pragma unroll
            for (int c = 0; c < 4; c++) s[j][c] = 0.f;

        #pragma unroll
        for (int ks = 0; ks < 4; ks++) {       // hd in k16 chunks
            uint32_t qh[4], ql[4];
            int qcb = ks * 32 + mat2 * 16;
            ldsm_x4(qh, sb + QHI + qrow * AP + qcb);
            ldsm_x4(ql, sb + QLO + qrow * AP + qcb);
            #pragma unroll
            for (int u = 0; u < 4; u++) {      // keys in n16 blocks
                uint32_t kh[4], kl[4];
                int row = 16 * u + rr + (mat2 << 3);
                int cb  = ks * 32 + mat1 * 16;
                ldsm_x4(kh, sb + KHI + row * AP + cb);
                ldsm_x4(kl, sb + KLO + row * AP + cb);
                #pragma unroll
                for (int jj = 0; jj < 2; jj++) {
                    const int j = 2 * u + jj, v = jj * 2;
                    mma_bf16(s[j], ql, kh[v], kh[v + 1]);
                    mma_bf16(s[j], qh, kl[v], kl[v + 1]);
                    mma_bf16(s[j], qh, kh[v], kh[v + 1]);
                }
            }
        }

        // online softmax (rows g and g+8; stats across the 4-lane quad)
        float mx0 = -1e30f, mx1 = -1e30f;
        #pragma unroll
        for (int j = 0; j < 8; j++) {
            mx0 = fmaxf(mx0, fmaxf(s[j][0], s[j][1]));
            mx1 = fmaxf(mx1, fmaxf(s[j][2], s[j][3]));
        }
        mx0 = fmaxf(mx0, __shfl_xor_sync(0xffffffffu, mx0, 1));
        mx0 = fmaxf(mx0, __shfl_xor_sync(0xffffffffu, mx0, 2));
        mx1 = fmaxf(mx1, __shfl_xor_sync(0xffffffffu, mx1, 1));
        mx1 = fmaxf(mx1, __shfl_xor_sync(0xffffffffu, mx1, 2));
        float m0n = fmaxf(m0, mx0), m1n = fmaxf(m1, mx1);
        float a0 = fexp2(m0 - m0n), a1 = fexp2(m1 - m1n);
        m0 = m0n; m1 = m1n;

        float rs0 = 0.f, rs1 = 0.f;
        #pragma unroll
        for (int j = 0; j < 8; j++) {
            s[j][0] = fexp2(s[j][0] - m0n);
            s[j][1] = fexp2(s[j][1] - m0n);
            s[j][2] = fexp2(s[j][2] - m1n);
            s[j][3] = fexp2(s[j][3] - m1n);
            rs0 += s[j][0] + s[j][1];
            rs1 += s[j][2] + s[j][3];
            o[j][0] *= a0; o[j][1] *= a0;
            o[j][2] *= a1; o[j][3] *= a1;
        }
        rs0 += __shfl_xor_sync(0xffffffffu, rs0, 1);
        rs0 += __shfl_xor_sync(0xffffffffu, rs0, 2);
        rs1 += __shfl_xor_sync(0xffffffffu, rs1, 1);
        rs1 += __shfl_xor_sync(0xffffffffu, rs1, 2);
        l0s = l0s * a0 + rs0;
        l1s = l1s * a1 + rs1;

        // O += P @ V, P built directly from S accumulators (no smem round-trip)
        #pragma unroll
        for (int ks = 0; ks < 4; ks++) {       // keys in k16 chunks
            uint32_t ph[4], pl[4];
            cvt_pair(s[2 * ks][0],     s[2 * ks][1],     ph[0], pl[0]);
            cvt_pair(s[2 * ks][2],     s[2 * ks][3],     ph[1], pl[1]);
            cvt_pair(s[2 * ks + 1][0], s[2 * ks + 1][1], ph[2], pl[2]);
            cvt_pair(s[2 * ks + 1][2], s[2 * ks + 1][3], ph[3], pl[3]);
            #pragma unroll
            for (int u = 0; u < 4; u++) {      // hd in n16 blocks
                uint32_t vh[4], vl[4];
                int row = 16 * u + rr + (mat2 << 3);
                int cb  = ks * 32 + mat1 * 16;
                ldsm_x4(vh, sb + VHI + row * AP + cb);
                ldsm_x4(vl, sb + VLO + row * AP + cb);
                #pragma unroll
                for (int jj = 0; jj < 2; jj++) {
                    const int j = 2 * u + jj, v = jj * 2;
                    mma_bf16(o[j], pl, vh[v], vh[v + 1]);
                    mma_bf16(o[j], ph, vl[v], vl[v + 1]);
                    mma_bf16(o[j], ph, vh[v], vh[v + 1]);
                }
            }
        }
    }

    const float inv0 = 1.f / l0s, inv1 = 1.f / l1s;
    const int g = lid >> 2, q = lid & 3;
    float* C0 = ctx + (tok0 + (size_t)qt * 128 + wid * 16 + g) * DMODEL + h * HDIM;
    float* C1 = C0 + (size_t)8 * DMODEL;
    #pragma unroll
    for (int j = 0; j < 8; j++) {
        int col = 8 * j + 2 * q;
        *(float2*)(C0 + col) = make_float2(o[j][0] * inv0, o[j][1] * inv0);
        *(float2*)(C1 + col) = make_float2(o[j][2] * inv1, o[j][3] * inv1);
    }
}

// ------------------------------ launch --------------------------------------
extern "C" void kernel_launch(void* const* d_in, const int* in_sizes, int n_in,
                              void* d_out, int out_size)
{
    const float* x   = (const float*)d_in[0];
    const float* Wq  = (const float*)d_in[1];
    const float* bq  = (const float*)d_in[2];
    const float* Wkd = (const float*)d_in[3];
    const float* bkd = (const float*)d_in[4];
    const float* Wvd = (const float*)d_in[5];
    const float* bvd = (const float*)d_in[6];
    const float* Wku = (const float*)d_in[7];
    const float* bku = (const float*)d_in[8];
    const float* Wvu = (const float*)d_in[9];
    const float* bvu = (const float*)d_in[10];
    const float* Wo  = (const float*)d_in[11];
    const float* bo  = (const float*)d_in[12];
    float* out = (float*)d_out;

    void *pQ, *pKL, *pVL, *pK, *pV, *pC;
    cudaGetSymbolAddress(&pQ,  g_Q);
    cudaGetSymbolAddress(&pKL, g_KL);
    cudaGetSymbolAddress(&pVL, g_VL);
    cudaGetSymbolAddress(&pK,  g_K);
    cudaGetSymbolAddress(&pV,  g_V);
    cudaGetSymbolAddress(&pC,  g_ctx);
    float* Qb  = (float*)pQ;
    float* KLb = (float*)pKL;
    float* VLb = (float*)pVL;
    float* Kb  = (float*)pK;
    float* Vb  = (float*)pV;
    float* Cb  = (float*)pC;

    cudaFuncSetAttribute(gemm_mma, cudaFuncAttributeMaxDynamicSharedMemorySize, GEMM_SMEM);
    cudaFuncSetAttribute(attn_mma, cudaFuncAttributeMaxDynamicSharedMemorySize, ATTN_SMEM);

    dim3 thr(256);
    // Q projection
    gemm_mma<<<dim3(DMODEL / 128, MROWS / 128, 1), thr, GEMM_SMEM>>>(
        x, Wq, bq, Qb,  x, Wq, bq, Qb,  MROWS, DMODEL, DMODEL);
    // latent down-projections, batched (z=2)
    gemm_mma<<<dim3(LATENT / 128, MROWS / 128, 2), thr, GEMM_SMEM>>>(
        x, Wkd, bkd, KLb,  x, Wvd, bvd, VLb,  MROWS, LATENT, DMODEL);
    // up-projections, batched (z=2)
    gemm_mma<<<dim3(DMODEL / 128, MROWS / 128, 2), thr, GEMM_SMEM>>>(
        KLb, Wku, bku, Kb,  VLb, Wvu, bvu, Vb,  MROWS, DMODEL, LATENT);
    // attention
    attn_mma<<<dim3(SEQ / 128, BATCH * NHEADS), thr, ATTN_SMEM>>>(Qb, Kb, Vb, Cb);
    // output projection
    gemm_mma<<<dim3(DMODEL / 128, MROWS / 128, 1), thr, GEMM_SMEM>>>(
        Cb, Wo, bo, out,  Cb, Wo, bo, out,  MROWS, DMODEL, DMODEL);
}

// round 7
// speedup vs baseline: 2.7470x; 1.0544x over previous
#include <cuda_runtime.h>
#include <cuda_bf16.h>
#include <cstdint>
#include <cstddef>

// ---------------------------------------------------------------------------
// MLA attention, bf16 split-precision mma.sync (m16n8k16).
//   B=2, S=2048, D_MODEL=1024, N_HEADS=16, HEAD_DIM=64, LATENT=256
// GEMMs: 3-term bf16 (hi/lo planes) -> ~fp32 accuracy.
// Attention: QK 2-term ((qh+ql)*kh, K bf16-only), PV 3-term.
// Q fragments hoisted to registers (loaded once per CTA).
// ---------------------------------------------------------------------------

#define BATCH    2
#define SEQ      2048
#define DMODEL   1024
#define NHEADS   16
#define HDIM     64
#define LATENT   256
#define MROWS    (BATCH * SEQ)     // 4096

// ------------------------- scratch (device globals) ------------------------
__device__ float g_Q  [MROWS * DMODEL];
__device__ float g_KL [MROWS * LATENT];
__device__ float g_VL [MROWS * LATENT];
__device__ float g_K  [MROWS * DMODEL];
__device__ float g_V  [MROWS * DMODEL];
__device__ float g_ctx[MROWS * DMODEL];

// ----------------------------- helpers -------------------------------------
__device__ __forceinline__ uint32_t smem_u32(const void* p) {
    uint32_t a;
    asm("{ .reg .u64 t; cvta.to.shared.u64 t, %1; cvt.u32.u64 %0, t; }"
        : "=r"(a) : "l"(p));
    return a;
}

__device__ __forceinline__ void ldsm_x4(uint32_t* r, uint32_t addr) {
    asm volatile("ldmatrix.sync.aligned.m8n8.x4.shared.b16 {%0,%1,%2,%3}, [%4];"
                 : "=r"(r[0]), "=r"(r[1]), "=r"(r[2]), "=r"(r[3])
                 : "r"(addr) : "memory");
}

// D += A(16x16) * B(16x8), bf16 inputs, fp32 acc
__device__ __forceinline__ void mma_bf16(float* d, const uint32_t* a,
                                         uint32_t b0, uint32_t b1) {
    asm volatile(
        "mma.sync.aligned.m16n8k16.row.col.f32.bf16.bf16.f32 "
        "{%0,%1,%2,%3}, {%4,%5,%6,%7}, {%8,%9}, {%0,%1,%2,%3};"
        : "+f"(d[0]), "+f"(d[1]), "+f"(d[2]), "+f"(d[3])
        : "r"(a[0]), "r"(a[1]), "r"(a[2]), "r"(a[3]), "r"(b0), "r"(b1));
}

// (f0,f1) -> packed bf16x2 hi and lo (lo = residual, bf16-rounded)
__device__ __forceinline__ void cvt_pair(float f0, float f1,
                                         uint32_t& hi, uint32_t& lo) {
    __nv_bfloat162 h = __floats2bfloat162_rn(f0, f1);
    uint32_t u = *reinterpret_cast<uint32_t*>(&h);
    float h0 = __uint_as_float(u << 16);
    float h1 = __uint_as_float(u & 0xffff0000u);
    __nv_bfloat162 l = __floats2bfloat162_rn(f0 - h0, f1 - h1);
    hi = u;
    lo = *reinterpret_cast<uint32_t*>(&l);
}
// hi only
__device__ __forceinline__ uint32_t cvt_hi(float f0, float f1) {
    __nv_bfloat162 h = __floats2bfloat162_rn(f0, f1);
    return *reinterpret_cast<uint32_t*>(&h);
}

// fast exp2 on the fma/alu pipes (MUFU is slow on B300). x <= 0, clamped.
__device__ __forceinline__ float fexp2(float x) {
    x = fmaxf(x, -100.0f);
    int   i = __float2int_rn(x);
    float f = x - (float)i;
    float p =               1.3333558e-3f;
    p = fmaf(p, f, 9.6181291e-3f);
    p = fmaf(p, f, 5.5504109e-2f);
    p = fmaf(p, f, 2.4022651e-1f);
    p = fmaf(p, f, 6.9314718e-1f);
    p = fmaf(p, f, 1.0f);
    return __uint_as_float((uint32_t)((i + 127) << 23)) * p;
}

// ------------------------------ bf16x3 GEMM ---------------------------------
// (unchanged from round 6)
#define GP     80
#define GPLANE 10240
#define GSTG   40960
#define GEMM_SMEM (2 * GSTG)
__global__ __launch_bounds__(256, 2) void gemm_mma(
    const float* __restrict__ A, const float* __restrict__ Bm,
    const float* __restrict__ bias, float* __restrict__ C,
    const float* __restrict__ A2, const float* __restrict__ Bm2,
    const float* __restrict__ bias2, float* __restrict__ C2,
    int M, int N, int K)
{
    extern __shared__ char smem[];
    const uint32_t sb = smem_u32(smem);

    if (blockIdx.z) { A = A2; Bm = Bm2; bias = bias2; C = C2; }

    const int tid = threadIdx.x;
    const int lid = tid & 31, wid = tid >> 5;
    const int bx = blockIdx.x, by = blockIdx.y;
    const int rr = lid & 7, mat1 = (lid >> 3) & 1, mat2 = lid >> 4;

    const float* Ab = A  + (size_t)by * 128 * K;
    const float* Bb = Bm + (size_t)bx * 128;

    const int Rm = (wid >> 2) * 64;
    const int Rn = (wid & 3) * 32;

    float acc[4][4][4];
    #pragma unroll
    for (int t = 0; t < 4; t++)
        #pragma unroll
        for (int j = 0; j < 4; j++)
            #pragma unroll
            for (int c = 0; c < 4; c++) acc[t][j][c] = 0.f;

    uint32_t ah8[8], al8[8], bh8[8], bl8[8];

    auto ldgA = [&](int k0) {
        #pragma unroll
        for (int p = 0; p < 4; p++) {
            int f4 = tid + p * 256;
            int r  = f4 >> 3;
            int c4 = (f4 & 7) << 2;
            float4 v = *(const float4*)(Ab + (size_t)r * K + k0 + c4);
            cvt_pair(v.x, v.y, ah8[2 * p],     al8[2 * p]);
            cvt_pair(v.z, v.w, ah8[2 * p + 1], al8[2 * p + 1]);
        }
    };
    auto ldgB = [&](int k0) {
        #pragma unroll
        for (int p = 0; p < 4; p++) {
            int idx = tid + p * 256;
            int n   = idx & 127;
            int kc  = (idx >> 7) << 2;
            const float* s0 = Bb + (size_t)(k0 + kc) * N + n;
            float v0 = s0[0];
            float v1 = s0[(size_t)N];
            float v2 = s0[(size_t)2 * N];
            float v3 = s0[(size_t)3 * N];
            cvt_pair(v0, v1, bh8[2 * p],     bl8[2 * p]);
            cvt_pair(v2, v3, bh8[2 * p + 1], bl8[2 * p + 1]);
        }
    };
    auto stsAB = [&](int s) {
        char* stg = smem + s * GSTG;
        #pragma unroll
        for (int p = 0; p < 4; p++) {
            int f4 = tid + p * 256;
            int r  = f4 >> 3;
            int c4 = (f4 & 7) << 2;
            char* a0 = stg + r * GP + c4 * 2;
            *(uint2*)(a0)          = make_uint2(ah8[2 * p], ah8[2 * p + 1]);
            *(uint2*)(a0 + GPLANE) = make_uint2(al8[2 * p], al8[2 * p + 1]);
        }
        #pragma unroll
        for (int p = 0; p < 4; p++) {
            int idx = tid + p * 256;
            int n   = idx & 127;
            int kc  = (idx >> 7) << 2;
            char* b0 = stg + 2 * GPLANE + n * GP + kc * 2;
            *(uint2*)(b0)          = make_uint2(bh8[2 * p], bh8[2 * p + 1]);
            *(uint2*)(b0 + GPLANE) = make_uint2(bl8[2 * p], bl8[2 * p + 1]);
        }
    };

    ldgA(0); ldgB(0); stsAB(0);
    __syncthreads();

    const int nk = K >> 5;
    for (int i = 0; i < nk; i++) {
        const int s = i & 1;
        if (i + 1 < nk) {
            ldgA((i + 1) << 5);
            ldgB((i + 1) << 5);
            stsAB(s ^ 1);
        }
        const uint32_t aBase = sb + s * GSTG;
        const uint32_t bBase = aBase + 2 * GPLANE;

        #pragma unroll
        for (int ks = 0; ks < 2; ks++) {
            uint32_t bh[2][4], bl[2][4];
            #pragma unroll
            for (int u = 0; u < 2; u++) {
                int row = Rn + 16 * u + rr + (mat2 << 3);
                int cb  = ks * 32 + mat1 * 16;
                ldsm_x4(bh[u], bBase + row * GP + cb);
                ldsm_x4(bl[u], bBase + GPLANE + row * GP + cb);
            }
            #pragma unroll
            for (int t = 0; t < 4; t++) {
                uint32_t ah[4], al[4];
                int row = Rm + 16 * t + rr + (mat1 << 3);
                int cb  = ks * 32 + mat2 * 16;
                ldsm_x4(ah, aBase + row * GP + cb);
                ldsm_x4(al, aBase + GPLANE + row * GP + cb);
                #pragma unroll
                for (int j = 0; j < 4; j++) {
                    const int u = j >> 1, v = (j & 1) * 2;
                    mma_bf16(acc[t][j], al, bh[u][v], bh[u][v + 1]);
                    mma_bf16(acc[t][j], ah, bl[u][v], bl[u][v + 1]);
                    mma_bf16(acc[t][j], ah, bh[u][v], bh[u][v + 1]);
                }
            }
        }
        __syncthreads();
    }

    const int g = lid >> 2, q = lid & 3;
    #pragma unroll
    for (int j = 0; j < 4; j++) {
        int col = bx * 128 + Rn + 8 * j + 2 * q;
        float b0 = bias[col], b1 = bias[col + 1];
        #pragma unroll
        for (int t = 0; t < 4; t++) {
            int row = by * 128 + Rm + 16 * t + g;
            *(float2*)(C + (size_t)row * N + col)
                = make_float2(acc[t][j][0] + b0, acc[t][j][1] + b1);
            *(float2*)(C + (size_t)(row + 8) * N + col)
                = make_float2(acc[t][j][2] + b0, acc[t][j][3] + b1);
        }
    }
}

// --------------------------- flash attention (mma) --------------------------
// grid (SEQ/128, BATCH*NHEADS), 256 threads = 8 warps, warp owns 16 q-rows.
// bf16 planes, pitch 144B per 64-elem row:
//   Qhi 0, Qlo 18432, Khi 36864, Vhi 46080, Vlo 55296 (total 64512).
// QK 2-term (no K-lo plane), PV 3-term. Q fragments hoisted to registers.
#define AP     144
#define QHI    0
#define QLO    18432
#define KHI    36864
#define VHI    46080
#define VLO    55296
#define ATTN_SMEM 64512
__global__ __launch_bounds__(256, 2) void attn_mma(
    const float* __restrict__ Q, const float* __restrict__ K,
    const float* __restrict__ V, float* __restrict__ ctx)
{
    extern __shared__ char smem[];
    const uint32_t sb = smem_u32(smem);

    const int tid = threadIdx.x;
    const int lid = tid & 31, wid = tid >> 5;
    const int rr = lid & 7, mat1 = (lid >> 3) & 1, mat2 = lid >> 4;
    const int qt = blockIdx.x, bh_ = blockIdx.y;
    const int b = bh_ >> 4, h = bh_ & 15;

    const float qscale = 0.125f * 1.44269504f;   // scale * log2(e)
    const size_t tok0 = (size_t)b * SEQ;
    const float* Qg = Q + (tok0 + (size_t)qt * 128) * DMODEL + h * HDIM;
    const float* Kg = K + tok0 * DMODEL + h * HDIM;
    const float* Vg = V + tok0 * DMODEL + h * HDIM;

    // Q (pre-scaled) -> bf16 planes
    #pragma unroll
    for (int p = 0; p < 8; p++) {
        int f4 = tid + p * 256;
        int r  = f4 >> 4;
        int c4 = (f4 & 15) << 2;
        float4 v = *(const float4*)(Qg + (size_t)r * DMODEL + c4);
        uint32_t h0, l0, h1, l1;
        cvt_pair(v.x * qscale, v.y * qscale, h0, l0);
        cvt_pair(v.z * qscale, v.w * qscale, h1, l1);
        char* a0 = smem + QHI + r * AP + c4 * 2;
        *(uint2*)(a0)               = make_uint2(h0, h1);
        *(uint2*)(a0 + (QLO - QHI)) = make_uint2(l0, l1);
    }
    __syncthreads();

    // hoist Q fragments (invariant across all 32 key tiles)
    const int qrow = wid * 16 + rr + (mat1 << 3);
    uint32_t qh[4][4], ql[4][4];
    #pragma unroll
    for (int ks = 0; ks < 4; ks++) {
        int cb = ks * 32 + mat2 * 16;
        ldsm_x4(qh[ks], sb + QHI + qrow * AP + cb);
        ldsm_x4(ql[ks], sb + QLO + qrow * AP + cb);
    }

    float o[8][4];
    #pragma unroll
    for (int j = 0; j < 8; j++)
        #pragma unroll
        for (int c = 0; c < 4; c++) o[j][c] = 0.f;
    float m0 = -1e30f, m1 = -1e30f, l0s = 0.f, l1s = 0.f;

    for (int kt = 0; kt < SEQ / 64; kt++) {
        __syncthreads();   // prior tile reads done before overwrite
        // K tile [key][hd] -> hi plane only
        #pragma unroll
        for (int p = 0; p < 4; p++) {
            int f4 = tid + p * 256;
            int r  = f4 >> 4;
            int c4 = (f4 & 15) << 2;
            float4 v = *(const float4*)(Kg + (size_t)(kt * 64 + r) * DMODEL + c4);
            uint32_t h0 = cvt_hi(v.x, v.y);
            uint32_t h1 = cvt_hi(v.z, v.w);
            *(uint2*)(smem + KHI + r * AP + c4 * 2) = make_uint2(h0, h1);
        }
        // V^T tile [hd][key] -> hi/lo planes (transpose gather)
        #pragma unroll
        for (int p = 0; p < 4; p++) {
            int idx = tid + p * 256;
            int hd  = idx >> 4;
            int kq  = (idx & 15) << 2;
            const float* s0 = Vg + (size_t)(kt * 64 + kq) * DMODEL + hd;
            float v0 = s0[0];
            float v1 = s0[DMODEL];
            float v2 = s0[2 * DMODEL];
            float v3 = s0[3 * DMODEL];
            uint32_t h0, l0, h1, l1;
            cvt_pair(v0, v1, h0, l0);
            cvt_pair(v2, v3, h1, l1);
            char* a0 = smem + VHI + hd * AP + kq * 2;
            *(uint2*)(a0)               = make_uint2(h0, h1);
            *(uint2*)(a0 + (VLO - VHI)) = make_uint2(l0, l1);
        }
        __syncthreads();

        // S = Q @ K^T  (2-term: (qh+ql)*kh; exp2 domain via qscale)
        float s[8][4];
        #pragma unroll
        for (int j = 0; j < 8; j++)
            #pragma unroll
            for (int c = 0; c < 4; c++) s[j][c] = 0.f;

        #pragma unroll
        for (int ks = 0; ks < 4; ks++) {
            #pragma unroll
            for (int u = 0; u < 4; u++) {
                uint32_t kh[4];
                int row = 16 * u + rr + (mat2 << 3);
                int cb  = ks * 32 + mat1 * 16;
                ldsm_x4(kh, sb + KHI + row * AP + cb);
                #pragma unroll
                for (int jj = 0; jj < 2; jj++) {
                    const int j = 2 * u + jj, v = jj * 2;
                    mma_bf16(s[j], ql[ks], kh[v], kh[v + 1]);
                    mma_bf16(s[j], qh[ks], kh[v], kh[v + 1]);
                }
            }
        }

        // online softmax (rows g and g+8; stats across the 4-lane quad)
        float mx0 = -1e30f, mx1 = -1e30f;
        #pragma unroll
        for (int j = 0; j < 8; j++) {
            mx0 = fmaxf(mx0, fmaxf(s[j][0], s[j][1]));
            mx1 = fmaxf(mx1, fmaxf(s[j][2], s[j][3]));
        }
        mx0 = fmaxf(mx0, __shfl_xor_sync(0xffffffffu, mx0, 1));
        mx0 = fmaxf(mx0, __shfl_xor_sync(0xffffffffu, mx0, 2));
        mx1 = fmaxf(mx1, __shfl_xor_sync(0xffffffffu, mx1, 1));
        mx1 = fmaxf(mx1, __shfl_xor_sync(0xffffffffu, mx1, 2));
        float m0n = fmaxf(m0, mx0), m1n = fmaxf(m1, mx1);
        float a0 = fexp2(m0 - m0n), a1 = fexp2(m1 - m1n);
        m0 = m0n; m1 = m1n;

        float rs0 = 0.f, rs1 = 0.f;
        #pragma unroll
        for (int j = 0; j < 8; j++) {
            s[j][0] = fexp2(s[j][0] - m0n);
            s[j][1] = fexp2(s[j][1] - m0n);
            s[j][2] = fexp2(s[j][2] - m1n);
            s[j][3] = fexp2(s[j][3] - m1n);
            rs0 += s[j][0] + s[j][1];
            rs1 += s[j][2] + s[j][3];
            o[j][0] *= a0; o[j][1] *= a0;
            o[j][2] *= a1; o[j][3] *= a1;
        }
        rs0 += __shfl_xor_sync(0xffffffffu, rs0, 1);
        rs0 += __shfl_xor_sync(0xffffffffu, rs0, 2);
        rs1 += __shfl_xor_sync(0xffffffffu, rs1, 1);
        rs1 += __shfl_xor_sync(0xffffffffu, rs1, 2);
        l0s = l0s * a0 + rs0;
        l1s = l1s * a1 + rs1;

        // O += P @ V (3-term), P built from S accumulators (registers only)
        #pragma unroll
        for (int ks = 0; ks < 4; ks++) {
            uint32_t ph[4], pl[4];
            cvt_pair(s[2 * ks][0],     s[2 * ks][1],     ph[0], pl[0]);
            cvt_pair(s[2 * ks][2],     s[2 * ks][3],     ph[1], pl[1]);
            cvt_pair(s[2 * ks + 1][0], s[2 * ks + 1][1], ph[2], pl[2]);
            cvt_pair(s[2 * ks + 1][2], s[2 * ks + 1][3], ph[3], pl[3]);
            #pragma unroll
            for (int u = 0; u < 4; u++) {
                uint32_t vh[4], vl[4];
                int row = 16 * u + rr + (mat2 << 3);
                int cb  = ks * 32 + mat1 * 16;
                ldsm_x4(vh, sb + VHI + row * AP + cb);
                ldsm_x4(vl, sb + VLO + row * AP + cb);
                #pragma unroll
                for (int jj = 0; jj < 2; jj++) {
                    const int j = 2 * u + jj, v = jj * 2;
                    mma_bf16(o[j], pl, vh[v], vh[v + 1]);
                    mma_bf16(o[j], ph, vl[v], vl[v + 1]);
                    mma_bf16(o[j], ph, vh[v], vh[v + 1]);
                }
            }
        }
    }

    const float inv0 = 1.f / l0s, inv1 = 1.f / l1s;
    const int g = lid >> 2, q = lid & 3;
    float* C0 = ctx + (tok0 + (size_t)qt * 128 + wid * 16 + g) * DMODEL + h * HDIM;
    float* C1 = C0 + (size_t)8 * DMODEL;
    #pragma unroll
    for (int j = 0; j < 8; j++) {
        int col = 8 * j + 2 * q;
        *(float2*)(C0 + col) = make_float2(o[j][0] * inv0, o[j][1] * inv0);
        *(float2*)(C1 + col) = make_float2(o[j][2] * inv1, o[j][3] * inv1);
    }
}

// ------------------------------ launch --------------------------------------
extern "C" void kernel_launch(void* const* d_in, const int* in_sizes, int n_in,
                              void* d_out, int out_size)
{
    const float* x   = (const float*)d_in[0];
    const float* Wq  = (const float*)d_in[1];
    const float* bq  = (const float*)d_in[2];
    const float* Wkd = (const float*)d_in[3];
    const float* bkd = (const float*)d_in[4];
    const float* Wvd = (const float*)d_in[5];
    const float* bvd = (const float*)d_in[6];
    const float* Wku = (const float*)d_in[7];
    const float* bku = (const float*)d_in[8];
    const float* Wvu = (const float*)d_in[9];
    const float* bvu = (const float*)d_in[10];
    const float* Wo  = (const float*)d_in[11];
    const float* bo  = (const float*)d_in[12];
    float* out = (float*)d_out;

    void *pQ, *pKL, *pVL, *pK, *pV, *pC;
    cudaGetSymbolAddress(&pQ,  g_Q);
    cudaGetSymbolAddress(&pKL, g_KL);
    cudaGetSymbolAddress(&pVL, g_VL);
    cudaGetSymbolAddress(&pK,  g_K);
    cudaGetSymbolAddress(&pV,  g_V);
    cudaGetSymbolAddress(&pC,  g_ctx);
    float* Qb  = (float*)pQ;
    float* KLb = (float*)pKL;
    float* VLb = (float*)pVL;
    float* Kb  = (float*)pK;
    float* Vb  = (float*)pV;
    float* Cb  = (float*)pC;

    cudaFuncSetAttribute(gemm_mma, cudaFuncAttributeMaxDynamicSharedMemorySize, GEMM_SMEM);
    cudaFuncSetAttribute(attn_mma, cudaFuncAttributeMaxDynamicSharedMemorySize, ATTN_SMEM);

    dim3 thr(256);
    gemm_mma<<<dim3(DMODEL / 128, MROWS / 128, 1), thr, GEMM_SMEM>>>(
        x, Wq, bq, Qb,  x, Wq, bq, Qb,  MROWS, DMODEL, DMODEL);
    gemm_mma<<<dim3(LATENT / 128, MROWS / 128, 2), thr, GEMM_SMEM>>>(
        x, Wkd, bkd, KLb,  x, Wvd, bvd, VLb,  MROWS, LATENT, DMODEL);
    gemm_mma<<<dim3(DMODEL / 128, MROWS / 128, 2), thr, GEMM_SMEM>>>(
        KLb, Wku, bku, Kb,  VLb, Wvu, bvu, Vb,  MROWS, DMODEL, LATENT);
    attn_mma<<<dim3(SEQ / 128, BATCH * NHEADS), thr, ATTN_SMEM>>>(Qb, Kb, Vb, Cb);
    gemm_mma<<<dim3(DMODEL / 128, MROWS / 128, 1), thr, GEMM_SMEM>>>(
        Cb, Wo, bo, out,  Cb, Wo, bo, out,  MROWS, DMODEL, DMODEL);
}

// round 8
// speedup vs baseline: 3.1895x; 1.1611x over previous
#include <cuda_runtime.h>
#include <cuda_bf16.h>
#include <cstdint>
#include <cstddef>

// ---------------------------------------------------------------------------
// MLA attention, bf16 split-precision mma.sync (m16n8k16).
//   B=2, S=2048, D_MODEL=1024, N_HEADS=16, HEAD_DIM=64, LATENT=256
// GEMMs: 3-term bf16 (hi/lo planes). Attention: QK 2-term, PV 3-term.
// Round 8: V stored in NATURAL [key][hd] layout (coalesced loader, same as K);
// PV B-fragments come from ldmatrix.trans — the uncoalesced V^T gather
// (32 lines/LDG, dominant L1 consumer in rounds 6-7) is gone.
// ---------------------------------------------------------------------------

#define BATCH    2
#define SEQ      2048
#define DMODEL   1024
#define NHEADS   16
#define HDIM     64
#define LATENT   256
#define MROWS    (BATCH * SEQ)     // 4096

// ------------------------- scratch (device globals) ------------------------
__device__ float g_Q  [MROWS * DMODEL];
__device__ float g_KL [MROWS * LATENT];
__device__ float g_VL [MROWS * LATENT];
__device__ float g_K  [MROWS * DMODEL];
__device__ float g_V  [MROWS * DMODEL];
__device__ float g_ctx[MROWS * DMODEL];

// ----------------------------- helpers -------------------------------------
__device__ __forceinline__ uint32_t smem_u32(const void* p) {
    uint32_t a;
    asm("{ .reg .u64 t; cvta.to.shared.u64 t, %1; cvt.u32.u64 %0, t; }"
        : "=r"(a) : "l"(p));
    return a;
}

__device__ __forceinline__ void ldsm_x4(uint32_t* r, uint32_t addr) {
    asm volatile("ldmatrix.sync.aligned.m8n8.x4.shared.b16 {%0,%1,%2,%3}, [%4];"
                 : "=r"(r[0]), "=r"(r[1]), "=r"(r[2]), "=r"(r[3])
                 : "r"(addr) : "memory");
}
__device__ __forceinline__ void ldsm_x4_t(uint32_t* r, uint32_t addr) {
    asm volatile("ldmatrix.sync.aligned.m8n8.x4.trans.shared.b16 {%0,%1,%2,%3}, [%4];"
                 : "=r"(r[0]), "=r"(r[1]), "=r"(r[2]), "=r"(r[3])
                 : "r"(addr) : "memory");
}

// D += A(16x16) * B(16x8), bf16 inputs, fp32 acc
__device__ __forceinline__ void mma_bf16(float* d, const uint32_t* a,
                                         uint32_t b0, uint32_t b1) {
    asm volatile(
        "mma.sync.aligned.m16n8k16.row.col.f32.bf16.bf16.f32 "
        "{%0,%1,%2,%3}, {%4,%5,%6,%7}, {%8,%9}, {%0,%1,%2,%3};"
        : "+f"(d[0]), "+f"(d[1]), "+f"(d[2]), "+f"(d[3])
        : "r"(a[0]), "r"(a[1]), "r"(a[2]), "r"(a[3]), "r"(b0), "r"(b1));
}

// (f0,f1) -> packed bf16x2 hi and lo (lo = residual, bf16-rounded)
__device__ __forceinline__ void cvt_pair(float f0, float f1,
                                         uint32_t& hi, uint32_t& lo) {
    __nv_bfloat162 h = __floats2bfloat162_rn(f0, f1);
    uint32_t u = *reinterpret_cast<uint32_t*>(&h);
    float h0 = __uint_as_float(u << 16);
    float h1 = __uint_as_float(u & 0xffff0000u);
    __nv_bfloat162 l = __floats2bfloat162_rn(f0 - h0, f1 - h1);
    hi = u;
    lo = *reinterpret_cast<uint32_t*>(&l);
}
__device__ __forceinline__ uint32_t cvt_hi(float f0, float f1) {
    __nv_bfloat162 h = __floats2bfloat162_rn(f0, f1);
    return *reinterpret_cast<uint32_t*>(&h);
}

// fast exp2 on the fma/alu pipes (MUFU is slow on B300). x <= 0, clamped.
__device__ __forceinline__ float fexp2(float x) {
    x = fmaxf(x, -100.0f);
    int   i = __float2int_rn(x);
    float f = x - (float)i;
    float p =               1.3333558e-3f;
    p = fmaf(p, f, 9.6181291e-3f);
    p = fmaf(p, f, 5.5504109e-2f);
    p = fmaf(p, f, 2.4022651e-1f);
    p = fmaf(p, f, 6.9314718e-1f);
    p = fmaf(p, f, 1.0f);
    return __uint_as_float((uint32_t)((i + 127) << 23)) * p;
}

// ------------------------------ bf16x3 GEMM ---------------------------------
// (unchanged from round 7)
#define GP     80
#define GPLANE 10240
#define GSTG   40960
#define GEMM_SMEM (2 * GSTG)
__global__ __launch_bounds__(256, 2) void gemm_mma(
    const float* __restrict__ A, const float* __restrict__ Bm,
    const float* __restrict__ bias, float* __restrict__ C,
    const float* __restrict__ A2, const float* __restrict__ Bm2,
    const float* __restrict__ bias2, float* __restrict__ C2,
    int M, int N, int K)
{
    extern __shared__ char smem[];
    const uint32_t sb = smem_u32(smem);

    if (blockIdx.z) { A = A2; Bm = Bm2; bias = bias2; C = C2; }

    const int tid = threadIdx.x;
    const int lid = tid & 31, wid = tid >> 5;
    const int bx = blockIdx.x, by = blockIdx.y;
    const int rr = lid & 7, mat1 = (lid >> 3) & 1, mat2 = lid >> 4;

    const float* Ab = A  + (size_t)by * 128 * K;
    const float* Bb = Bm + (size_t)bx * 128;

    const int Rm = (wid >> 2) * 64;
    const int Rn = (wid & 3) * 32;

    float acc[4][4][4];
    #pragma unroll
    for (int t = 0; t < 4; t++)
        #pragma unroll
        for (int j = 0; j < 4; j++)
            #pragma unroll
            for (int c = 0; c < 4; c++) acc[t][j][c] = 0.f;

    uint32_t ah8[8], al8[8], bh8[8], bl8[8];

    auto ldgA = [&](int k0) {
        #pragma unroll
        for (int p = 0; p < 4; p++) {
            int f4 = tid + p * 256;
            int r  = f4 >> 3;
            int c4 = (f4 & 7) << 2;
            float4 v = *(const float4*)(Ab + (size_t)r * K + k0 + c4);
            cvt_pair(v.x, v.y, ah8[2 * p],     al8[2 * p]);
            cvt_pair(v.z, v.w, ah8[2 * p + 1], al8[2 * p + 1]);
        }
    };
    auto ldgB = [&](int k0) {
        #pragma unroll
        for (int p = 0; p < 4; p++) {
            int idx = tid + p * 256;
            int n   = idx & 127;
            int kc  = (idx >> 7) << 2;
            const float* s0 = Bb + (size_t)(k0 + kc) * N + n;
            float v0 = s0[0];
            float v1 = s0[(size_t)N];
            float v2 = s0[(size_t)2 * N];
            float v3 = s0[(size_t)3 * N];
            cvt_pair(v0, v1, bh8[2 * p],     bl8[2 * p]);
            cvt_pair(v2, v3, bh8[2 * p + 1], bl8[2 * p + 1]);
        }
    };
    auto stsAB = [&](int s) {
        char* stg = smem + s * GSTG;
        #pragma unroll
        for (int p = 0; p < 4; p++) {
            int f4 = tid + p * 256;
            int r  = f4 >> 3;
            int c4 = (f4 & 7) << 2;
            char* a0 = stg + r * GP + c4 * 2;
            *(uint2*)(a0)          = make_uint2(ah8[2 * p], ah8[2 * p + 1]);
            *(uint2*)(a0 + GPLANE) = make_uint2(al8[2 * p], al8[2 * p + 1]);
        }
        #pragma unroll
        for (int p = 0; p < 4; p++) {
            int idx = tid + p * 256;
            int n   = idx & 127;
            int kc  = (idx >> 7) << 2;
            char* b0 = stg + 2 * GPLANE + n * GP + kc * 2;
            *(uint2*)(b0)          = make_uint2(bh8[2 * p], bh8[2 * p + 1]);
            *(uint2*)(b0 + GPLANE) = make_uint2(bl8[2 * p], bl8[2 * p + 1]);
        }
    };

    ldgA(0); ldgB(0); stsAB(0);
    __syncthreads();

    const int nk = K >> 5;
    for (int i = 0; i < nk; i++) {
        const int s = i & 1;
        if (i + 1 < nk) {
            ldgA((i + 1) << 5);
            ldgB((i + 1) << 5);
            stsAB(s ^ 1);
        }
        const uint32_t aBase = sb + s * GSTG;
        const uint32_t bBase = aBase + 2 * GPLANE;

        #pragma unroll
        for (int ks = 0; ks < 2; ks++) {
            uint32_t bh[2][4], bl[2][4];
            #pragma unroll
            for (int u = 0; u < 2; u++) {
                int row = Rn + 16 * u + rr + (mat2 << 3);
                int cb  = ks * 32 + mat1 * 16;
                ldsm_x4(bh[u], bBase + row * GP + cb);
                ldsm_x4(bl[u], bBase + GPLANE + row * GP + cb);
            }
            #pragma unroll
            for (int t = 0; t < 4; t++) {
                uint32_t ah[4], al[4];
                int row = Rm + 16 * t + rr + (mat1 << 3);
                int cb  = ks * 32 + mat2 * 16;
                ldsm_x4(ah, aBase + row * GP + cb);
                ldsm_x4(al, aBase + GPLANE + row * GP + cb);
                #pragma unroll
                for (int j = 0; j < 4; j++) {
                    const int u = j >> 1, v = (j & 1) * 2;
                    mma_bf16(acc[t][j], al, bh[u][v], bh[u][v + 1]);
                    mma_bf16(acc[t][j], ah, bl[u][v], bl[u][v + 1]);
                    mma_bf16(acc[t][j], ah, bh[u][v], bh[u][v + 1]);
                }
            }
        }
        __syncthreads();
    }

    const int g = lid >> 2, q = lid & 3;
    #pragma unroll
    for (int j = 0; j < 4; j++) {
        int col = bx * 128 + Rn + 8 * j + 2 * q;
        float b0 = bias[col], b1 = bias[col + 1];
        #pragma unroll
        for (int t = 0; t < 4; t++) {
            int row = by * 128 + Rm + 16 * t + g;
            *(float2*)(C + (size_t)row * N + col)
                = make_float2(acc[t][j][0] + b0, acc[t][j][1] + b1);
            *(float2*)(C + (size_t)(row + 8) * N + col)
                = make_float2(acc[t][j][2] + b0, acc[t][j][3] + b1);
        }
    }
}

// --------------------------- flash attention (mma) --------------------------
// grid (SEQ/128, BATCH*NHEADS), 256 threads = 8 warps, warp owns 16 q-rows.
// bf16 planes, pitch 144B per 64-elem row:
//   Qhi 0, Qlo 18432, Khi 36864, Vhi 46080 (natural [key][hd]), Vlo 55296.
// QK 2-term, PV 3-term with ldmatrix.trans B-fragments from natural V.
#define AP     144
#define QHI    0
#define QLO    18432
#define KHI    36864
#define VHI    46080
#define VLO    55296
#define ATTN_SMEM 64512
__global__ __launch_bounds__(256, 2) void attn_mma(
    const float* __restrict__ Q, const float* __restrict__ K,
    const float* __restrict__ V, float* __restrict__ ctx)
{
    extern __shared__ char smem[];
    const uint32_t sb = smem_u32(smem);

    const int tid = threadIdx.x;
    const int lid = tid & 31, wid = tid >> 5;
    const int rr = lid & 7, mat1 = (lid >> 3) & 1, mat2 = lid >> 4;
    const int qt = blockIdx.x, bh_ = blockIdx.y;
    const int b = bh_ >> 4, h = bh_ & 15;

    const float qscale = 0.125f * 1.44269504f;   // scale * log2(e)
    const size_t tok0 = (size_t)b * SEQ;
    const float* Qg = Q + (tok0 + (size_t)qt * 128) * DMODEL + h * HDIM;
    const float* Kg = K + tok0 * DMODEL + h * HDIM;
    const float* Vg = V + tok0 * DMODEL + h * HDIM;

    // Q (pre-scaled) -> bf16 planes
    #pragma unroll
    for (int p = 0; p < 8; p++) {
        int f4 = tid + p * 256;
        int r  = f4 >> 4;
        int c4 = (f4 & 15) << 2;
        float4 v = *(const float4*)(Qg + (size_t)r * DMODEL + c4);
        uint32_t h0, l0, h1, l1;
        cvt_pair(v.x * qscale, v.y * qscale, h0, l0);
        cvt_pair(v.z * qscale, v.w * qscale, h1, l1);
        char* a0 = smem + QHI + r * AP + c4 * 2;
        *(uint2*)(a0)               = make_uint2(h0, h1);
        *(uint2*)(a0 + (QLO - QHI)) = make_uint2(l0, l1);
    }
    __syncthreads();

    // hoist Q fragments (invariant across all 32 key tiles)
    const int qrow = wid * 16 + rr + (mat1 << 3);
    uint32_t qh[4][4], ql[4][4];
    #pragma unroll
    for (int ks = 0; ks < 4; ks++) {
        int cb = ks * 32 + mat2 * 16;
        ldsm_x4(qh[ks], sb + QHI + qrow * AP + cb);
        ldsm_x4(ql[ks], sb + QLO + qrow * AP + cb);
    }

    float o[8][4];
    #pragma unroll
    for (int j = 0; j < 8; j++)
        #pragma unroll
        for (int c = 0; c < 4; c++) o[j][c] = 0.f;
    float m0 = -1e30f, m1 = -1e30f, l0s = 0.f, l1s = 0.f;

    // PV trans-fragment addressing (lane -> matrix mapping):
    //   key row = ks*16 + ((lid>>3)&1)*8 + rr,  hd byte = u*32 + (lid>>4)*16
    const int vrow_off = ((lid >> 3) & 1) * 8 + rr;
    const int vcol_off = (lid >> 4) * 16;

    for (int kt = 0; kt < SEQ / 64; kt++) {
        __syncthreads();   // prior tile reads done before overwrite
        // K tile [key][hd] -> hi plane only (coalesced)
        #pragma unroll
        for (int p = 0; p < 4; p++) {
            int f4 = tid + p * 256;
            int r  = f4 >> 4;
            int c4 = (f4 & 15) << 2;
            float4 v = *(const float4*)(Kg + (size_t)(kt * 64 + r) * DMODEL + c4);
            uint32_t h0 = cvt_hi(v.x, v.y);
            uint32_t h1 = cvt_hi(v.z, v.w);
            *(uint2*)(smem + KHI + r * AP + c4 * 2) = make_uint2(h0, h1);
        }
        // V tile [key][hd] natural -> hi/lo planes (coalesced, same as K)
        #pragma unroll
        for (int p = 0; p < 4; p++) {
            int f4 = tid + p * 256;
            int r  = f4 >> 4;
            int c4 = (f4 & 15) << 2;
            float4 v = *(const float4*)(Vg + (size_t)(kt * 64 + r) * DMODEL + c4);
            uint32_t h0, l0, h1, l1;
            cvt_pair(v.x, v.y, h0, l0);
            cvt_pair(v.z, v.w, h1, l1);
            char* a0 = smem + VHI + r * AP + c4 * 2;
            *(uint2*)(a0)               = make_uint2(h0, h1);
            *(uint2*)(a0 + (VLO - VHI)) = make_uint2(l0, l1);
        }
        __syncthreads();

        // S = Q @ K^T  (2-term: (qh+ql)*kh; exp2 domain via qscale)
        float s[8][4];
        #pragma unroll
        for (int j = 0; j < 8; j++)
            #pragma unroll
            for (int c = 0; c < 4; c++) s[j][c] = 0.f;

        #pragma unroll
        for (int ks = 0; ks < 4; ks++) {
            #pragma unroll
            for (int u = 0; u < 4; u++) {
                uint32_t kh[4];
                int row = 16 * u + rr + (mat2 << 3);
                int cb  = ks * 32 + mat1 * 16;
                ldsm_x4(kh, sb + KHI + row * AP + cb);
                #pragma unroll
                for (int jj = 0; jj < 2; jj++) {
                    const int j = 2 * u + jj, v = jj * 2;
                    mma_bf16(s[j], ql[ks], kh[v], kh[v + 1]);
                    mma_bf16(s[j], qh[ks], kh[v], kh[v + 1]);
                }
            }
        }

        // online softmax (rows g and g+8; stats across the 4-lane quad)
        float mx0 = -1e30f, mx1 = -1e30f;
        #pragma unroll
        for (int j = 0; j < 8; j++) {
            mx0 = fmaxf(mx0, fmaxf(s[j][0], s[j][1]));
            mx1 = fmaxf(mx1, fmaxf(s[j][2], s[j][3]));
        }
        mx0 = fmaxf(mx0, __shfl_xor_sync(0xffffffffu, mx0, 1));
        mx0 = fmaxf(mx0, __shfl_xor_sync(0xffffffffu, mx0, 2));
        mx1 = fmaxf(mx1, __shfl_xor_sync(0xffffffffu, mx1, 1));
        mx1 = fmaxf(mx1, __shfl_xor_sync(0xffffffffu, mx1, 2));
        float m0n = fmaxf(m0, mx0), m1n = fmaxf(m1, mx1);
        float a0 = fexp2(m0 - m0n), a1 = fexp2(m1 - m1n);
        m0 = m0n; m1 = m1n;

        float rs0 = 0.f, rs1 = 0.f;
        #pragma unroll
        for (int j = 0; j < 8; j++) {
            s[j][0] = fexp2(s[j][0] - m0n);
            s[j][1] = fexp2(s[j][1] - m0n);
            s[j][2] = fexp2(s[j][2] - m1n);
            s[j][3] = fexp2(s[j][3] - m1n);
            rs0 += s[j][0] + s[j][1];
            rs1 += s[j][2] + s[j][3];
            o[j][0] *= a0; o[j][1] *= a0;
            o[j][2] *= a1; o[j][3] *= a1;
        }
        rs0 += __shfl_xor_sync(0xffffffffu, rs0, 1);
        rs0 += __shfl_xor_sync(0xffffffffu, rs0, 2);
        rs1 += __shfl_xor_sync(0xffffffffu, rs1, 1);
        rs1 += __shfl_xor_sync(0xffffffffu, rs1, 2);
        l0s = l0s * a0 + rs0;
        l1s = l1s * a1 + rs1;

        // O += P @ V (3-term), V fragments via ldmatrix.trans from natural tile
        #pragma unroll
        for (int ks = 0; ks < 4; ks++) {
            uint32_t ph[4], pl[4];
            cvt_pair(s[2 * ks][0],     s[2 * ks][1],     ph[0], pl[0]);
            cvt_pair(s[2 * ks][2],     s[2 * ks][3],     ph[1], pl[1]);
            cvt_pair(s[2 * ks + 1][0], s[2 * ks + 1][1], ph[2], pl[2]);
            cvt_pair(s[2 * ks + 1][2], s[2 * ks + 1][3], ph[3], pl[3]);
            const int vrow = ks * 16 + vrow_off;
            #pragma unroll
            for (int u = 0; u < 4; u++) {
                uint32_t vh[4], vl[4];
                int cb = u * 32 + vcol_off;
                ldsm_x4_t(vh, sb + VHI + vrow * AP + cb);
                ldsm_x4_t(vl, sb + VLO + vrow * AP + cb);
                #pragma unroll
                for (int jj = 0; jj < 2; jj++) {
                    const int j = 2 * u + jj, v = jj * 2;
                    mma_bf16(o[j], pl, vh[v], vh[v + 1]);
                    mma_bf16(o[j], ph, vl[v], vl[v + 1]);
                    mma_bf16(o[j], ph, vh[v], vh[v + 1]);
                }
            }
        }
    }

    const float inv0 = 1.f / l0s, inv1 = 1.f / l1s;
    const int g = lid >> 2, q = lid & 3;
    float* C0 = ctx + (tok0 + (size_t)qt * 128 + wid * 16 + g) * DMODEL + h * HDIM;
    float* C1 = C0 + (size_t)8 * DMODEL;
    #pragma unroll
    for (int j = 0; j < 8; j++) {
        int col = 8 * j + 2 * q;
        *(float2*)(C0 + col) = make_float2(o[j][0] * inv0, o[j][1] * inv0);
        *(float2*)(C1 + col) = make_float2(o[j][2] * inv1, o[j][3] * inv1);
    }
}

// ------------------------------ launch --------------------------------------
extern "C" void kernel_launch(void* const* d_in, const int* in_sizes, int n_in,
                              void* d_out, int out_size)
{
    const float* x   = (const float*)d_in[0];
    const float* Wq  = (const float*)d_in[1];
    const float* bq  = (const float*)d_in[2];
    const float* Wkd = (const float*)d_in[3];
    const float* bkd = (const float*)d_in[4];
    const float* Wvd = (const float*)d_in[5];
    const float* bvd = (const float*)d_in[6];
    const float* Wku = (const float*)d_in[7];
    const float* bku = (const float*)d_in[8];
    const float* Wvu = (const float*)d_in[9];
    const float* bvu = (const float*)d_in[10];
    const float* Wo  = (const float*)d_in[11];
    const float* bo  = (const float*)d_in[12];
    float* out = (float*)d_out;

    void *pQ, *pKL, *pVL, *pK, *pV, *pC;
    cudaGetSymbolAddress(&pQ,  g_Q);
    cudaGetSymbolAddress(&pKL, g_KL);
    cudaGetSymbolAddress(&pVL, g_VL);
    cudaGetSymbolAddress(&pK,  g_K);
    cudaGetSymbolAddress(&pV,  g_V);
    cudaGetSymbolAddress(&pC,  g_ctx);
    float* Qb  = (float*)pQ;
    float* KLb = (float*)pKL;
    float* VLb = (float*)pVL;
    float* Kb  = (float*)pK;
    float* Vb  = (float*)pV;
    float* Cb  = (float*)pC;

    cudaFuncSetAttribute(gemm_mma, cudaFuncAttributeMaxDynamicSharedMemorySize, GEMM_SMEM);
    cudaFuncSetAttribute(attn_mma, cudaFuncAttributeMaxDynamicSharedMemorySize, ATTN_SMEM);

    dim3 thr(256);
    gemm_mma<<<dim3(DMODEL / 128, MROWS / 128, 1), thr, GEMM_SMEM>>>(
        x, Wq, bq, Qb,  x, Wq, bq, Qb,  MROWS, DMODEL, DMODEL);
    gemm_mma<<<dim3(LATENT / 128, MROWS / 128, 2), thr, GEMM_SMEM>>>(
        x, Wkd, bkd, KLb,  x, Wvd, bvd, VLb,  MROWS, LATENT, DMODEL);
    gemm_mma<<<dim3(DMODEL / 128, MROWS / 128, 2), thr, GEMM_SMEM>>>(
        KLb, Wku, bku, Kb,  VLb, Wvu, bvu, Vb,  MROWS, DMODEL, LATENT);
    attn_mma<<<dim3(SEQ / 128, BATCH * NHEADS), thr, ATTN_SMEM>>>(Qb, Kb, Vb, Cb);
    gemm_mma<<<dim3(DMODEL / 128, MROWS / 128, 1), thr, GEMM_SMEM>>>(
        Cb, Wo, bo, out,  Cb, Wo, bo, out,  MROWS, DMODEL, DMODEL);
}